// round 6
// baseline (speedup 1.0000x reference)
#include <cuda_runtime.h>
#include <cstdint>

#define NTOK 4096
#define DIM  1024
#define NEXP 8
#define HID  4096
#define THR  0.3f

#define BM 128
#define BN 256
#define BK 16
#define BSTG 4352   // floats per B stage (32 groups * 136)

// ---------------- scratch (static device memory; no allocs anywhere) ----------------
__device__ float g_c[NTOK * NEXP];
__device__ int   g_idx[NEXP][NTOK];
__device__ float g_wt[NEXP][NTOK];
__device__ int   g_cnt[NEXP];
// fragment-layout A operands (see frag_off): tiles of 128 rows x 8 k
__device__ __align__(16) float g_af[(size_t)NEXP * NTOK * DIM];   // gathered+rounded expert inputs
__device__ __align__(16) float g_hf[(size_t)NEXP * NTOK * HID];   // gelu hidden, rounded

// ---------------- helpers ----------------
__device__ __forceinline__ uint32_t f2tf(float f) {
    uint32_t u;
    asm("cvt.rna.tf32.f32 %0, %1;" : "=r"(u) : "f"(f));
    return u;
}
__device__ __forceinline__ float rnatf(float f) { return __uint_as_float(f2tf(f)); }

// float-index of element (row r in 128-row tile st, col k) of expert e in fragment layout.
// KQ = K/8 quads. Fragment: [e*32+st][ksq][t16][lane][q] ; lane=((r&7)<<2)|(k&3),
// q = bit3(r) | bit2(k)<<1  -> matches mma.m16n8k8 A-fragment (a0..a3).
__device__ __forceinline__ size_t frag_off(int e, int st, int KQ, int r, int k) {
    size_t blk = (((size_t)(e * 32 + st) * KQ + (k >> 3)) * 8 + (r >> 4)) * 128;
    int lane = ((r & 7) << 2) | (k & 3);
    int q = ((r >> 3) & 1) | (((k >> 2) & 1) << 1);
    return blk + (size_t)(lane << 2) + q;
}

__device__ __forceinline__ void mma8v(float* c, const uint4& a, const uint32_t* b) {
    asm volatile(
        "mma.sync.aligned.m16n8k8.row.col.f32.tf32.tf32.f32 "
        "{%0,%1,%2,%3}, {%4,%5,%6,%7}, {%8,%9}, {%0,%1,%2,%3};"
        : "+f"(c[0]), "+f"(c[1]), "+f"(c[2]), "+f"(c[3])
        : "r"(a.x), "r"(a.y), "r"(a.z), "r"(a.w), "r"(b[0]), "r"(b[1]));
}

__device__ __forceinline__ float gelu_exact(float v) {
    return 0.5f * v * (1.0f + erff(v * 0.70710678118654752f));
}

// ---------------- kernel 1: gate scores, combine weights, out init with sum(c*b2) ----------------
__global__ __launch_bounds__(256) void gate_kernel(
    const float* __restrict__ x, const float* __restrict__ wg,
    const float* __restrict__ bg, const float* __restrict__ b2,
    float* __restrict__ out)
{
    __shared__ float wgs[DIM * 9];
    int tid = threadIdx.x;
    for (int i = tid; i < DIM * NEXP; i += 256)
        wgs[(i >> 3) * 9 + (i & 7)] = wg[i];
    __syncthreads();

    int lane = tid & 31, wid = tid >> 5;
    int n = blockIdx.x * 8 + wid;

    float s[NEXP];
#pragma unroll
    for (int e = 0; e < NEXP; e++) s[e] = 0.f;

    const float* xr = x + (size_t)n * DIM;
    for (int k = lane; k < DIM; k += 32) {
        float xv = xr[k];
#pragma unroll
        for (int e = 0; e < NEXP; e++) s[e] += xv * wgs[k * 9 + e];
    }
#pragma unroll
    for (int e = 0; e < NEXP; e++)
#pragma unroll
        for (int o = 16; o; o >>= 1)
            s[e] += __shfl_xor_sync(0xffffffffu, s[e], o);

    float mx = -1e30f;
#pragma unroll
    for (int e = 0; e < NEXP; e++) { s[e] += bg[e]; mx = fmaxf(mx, s[e]); }
    float sum = 0.f;
#pragma unroll
    for (int e = 0; e < NEXP; e++) { s[e] = expf(s[e] - mx); sum += s[e]; }
    float inv = 1.f / sum;
#pragma unroll
    for (int e = 0; e < NEXP; e++) s[e] *= inv;

    if (lane == 0) {
        float* gs = out + (size_t)NTOK * DIM + (size_t)n * NEXP;
#pragma unroll
        for (int e = 0; e < NEXP; e++) gs[e] = s[e];
    }

    float msum = 0.f; int cnt = 0;
#pragma unroll
    for (int e = 0; e < NEXP; e++) if (s[e] >= THR) { msum += s[e]; cnt++; }
    int top1 = 0; float best = s[0];
#pragma unroll
    for (int e = 1; e < NEXP; e++) if (s[e] > best) { best = s[e]; top1 = e; }
    float dn = 1.f / (msum + 1e-6f);
    float c[NEXP];
#pragma unroll
    for (int e = 0; e < NEXP; e++)
        c[e] = cnt ? ((s[e] >= THR) ? s[e] * dn : 0.f) : ((e == top1) ? 1.f : 0.f);

    if (lane == 0) {
#pragma unroll
        for (int e = 0; e < NEXP; e++) g_c[n * NEXP + e] = c[e];
    }

    for (int d = lane; d < DIM; d += 32) {
        float a = 0.f;
#pragma unroll
        for (int e = 0; e < NEXP; e++) a += c[e] * b2[e * DIM + d];
        out[(size_t)n * DIM + d] = a;
    }
}

// ---------------- kernel 2: per-expert compaction, 1 CTA per expert ----------------
__global__ __launch_bounds__(256) void compact_kernel()
{
    const int e = blockIdx.x;
    __shared__ int wsum[8];
    __shared__ int wbase[9];
    const int tid = threadIdx.x, lane = tid & 31, wid = tid >> 5;

    int base = 0;
#pragma unroll
    for (int c0 = 0; c0 < NTOK; c0 += 256) {
        int n = c0 + tid;
        float c = g_c[n * NEXP + e];
        unsigned m = __ballot_sync(0xffffffffu, c > 0.f);
        if (lane == 0) wsum[wid] = __popc(m);
        __syncthreads();
        if (tid == 0) {
            int acc = 0;
#pragma unroll
            for (int w = 0; w < 8; w++) { wbase[w] = acc; acc += wsum[w]; }
            wbase[8] = acc;
        }
        __syncthreads();
        if (c > 0.f) {
            int pos = base + wbase[wid] + __popc(m & ((1u << lane) - 1u));
            g_idx[e][pos] = n;
            g_wt[e][pos]  = c;
        }
        base += wbase[8];
        __syncthreads();
    }
    if (tid == 0) g_cnt[e] = base;
}

// ---------------- kernel 2b: gather + tf32-round expert inputs into fragment layout ----------------
__global__ __launch_bounds__(256) void permA_kernel(const float* __restrict__ ei)
{
    const int st = blockIdx.x;
    const int e  = blockIdx.y;
    const int me = g_cnt[e];
    if (st * BM >= me) return;
    const int tid  = threadIdx.x;
    const int r    = tid >> 1;          // 0..127 row in tile
    const int half = tid & 1;           // 0..1: k halves of 512
    const int ss = st * BM + r;
    if (ss >= me) return;
    const int tok = g_idx[e][ss];
    const float4* src = (const float4*)(ei + ((size_t)e * NTOK + tok) * DIM) + half * 128;

#pragma unroll 4
    for (int kq = 0; kq < 128; kq++) {
        int k = half * 512 + kq * 4;
        float4 v = src[kq];
        size_t o = frag_off(e, st, DIM / 8, r, k);
        g_af[o +  0] = rnatf(v.x);
        g_af[o +  4] = rnatf(v.y);
        g_af[o +  8] = rnatf(v.z);
        g_af[o + 12] = rnatf(v.w);
    }
}

// =====================================================================================
// FFN GEMMs: 8 warps/CTA (2 M x 4 N of 64x64 warp tiles), CTA tile 128x256, BK=16.
// A: direct fragment LDG.128 from permuted global (no smem). B: double-buffered smem.
// =====================================================================================

// ---------------- kernel 3: grouped GEMM1: hf = frag(gelu(A @ w1 + b1)) ----------------
__global__ __launch_bounds__(256, 1) void ffn1_kernel(
    const float* __restrict__ w1, const float* __restrict__ b1)
{
    __shared__ float Bs[2 * BSTG];

    const int e  = blockIdx.z;
    const int me = g_cnt[e];
    const int mt = blockIdx.x;
    if (mt * BM >= me) return;
    const int n0 = blockIdx.y * BN;

    const int tid  = threadIdx.x;
    const int lane = tid & 31;
    const int wid  = tid >> 5;
    const int wm   = wid >> 2;     // 0..1
    const int wn   = wid & 3;      // 0..3
    const int g    = lane >> 2;
    const int t    = lane & 3;

    // A fragment base (uint4 units)
    const uint4* aF = (const uint4*)g_af;
    const size_t aBase = (((size_t)(e * 32 + mt) * (DIM / 8)) * 8 + wm * 4) * 32 + lane;

    // B loader: thread covers col quad n4 = (tid&63)*4, rows k = (tid>>6) + 4i
    const int bk = tid >> 6;                 // 0..3
    const int n4 = (tid & 63) << 2;          // 0..252
    const float* bptr = w1 + (size_t)e * DIM * HID + n0 + n4;
    const int bofs = ((tid & 63) >> 1) * 136 + 4 * (tid & 1);

    float acc[4][8][4];
#pragma unroll
    for (int a = 0; a < 4; a++)
#pragma unroll
        for (int b = 0; b < 8; b++)
#pragma unroll
            for (int q = 0; q < 4; q++) acc[a][b][q] = 0.f;

    uint4 afc[2][4], afn[2][4];
    float4 pb[4];

    // prime
#pragma unroll
    for (int ks = 0; ks < 2; ks++)
#pragma unroll
        for (int mi = 0; mi < 4; mi++)
            afc[ks][mi] = aF[aBase + (size_t)ks * 256 + mi * 32];
#pragma unroll
    for (int i = 0; i < 4; i++)
        pb[i] = *(const float4*)(bptr + (size_t)(bk + 4 * i) * HID);
#pragma unroll
    for (int i = 0; i < 4; i++) {
        float4 v = make_float4(rnatf(pb[i].x), rnatf(pb[i].y), rnatf(pb[i].z), rnatf(pb[i].w));
        *(float4*)(Bs + bofs + (bk + 4 * i) * 8) = v;
    }
    __syncthreads();

    const int KT = DIM / BK;   // 64
    for (int kt = 0; kt < KT; kt++) {
        const int cur = (kt & 1) * BSTG;
        const bool more = (kt + 1 < KT);
        if (more) {
#pragma unroll
            for (int ks = 0; ks < 2; ks++)
#pragma unroll
                for (int mi = 0; mi < 4; mi++)
                    afn[ks][mi] = aF[aBase + (size_t)((kt + 1) * 2 + ks) * 256 + mi * 32];
            const float* bp = bptr + (size_t)(kt + 1) * BK * HID;
#pragma unroll
            for (int i = 0; i < 4; i++)
                pb[i] = *(const float4*)(bp + (size_t)(bk + 4 * i) * HID);
        }
#pragma unroll
        for (int ks = 0; ks < 2; ks++) {
            const int k0 = ks * 8;
#pragma unroll
            for (int ni = 0; ni < 8; ni++) {
                int G = wn * 8 + ni;
                uint32_t bf[2];
                bf[0] = __float_as_uint(Bs[cur + G * 136 + (k0 + t) * 8 + g]);
                bf[1] = __float_as_uint(Bs[cur + G * 136 + (k0 + t + 4) * 8 + g]);
#pragma unroll
                for (int mi = 0; mi < 4; mi++)
                    mma8v(acc[mi][ni], afc[ks][mi], bf);
            }
        }
        if (more) {
            const int nxt = ((kt + 1) & 1) * BSTG;
#pragma unroll
            for (int i = 0; i < 4; i++) {
                float4 v = make_float4(rnatf(pb[i].x), rnatf(pb[i].y), rnatf(pb[i].z), rnatf(pb[i].w));
                *(float4*)(Bs + nxt + bofs + (bk + 4 * i) * 8) = v;
            }
#pragma unroll
            for (int ks = 0; ks < 2; ks++)
#pragma unroll
                for (int mi = 0; mi < 4; mi++)
                    afc[ks][mi] = afn[ks][mi];
        }
        __syncthreads();
    }

    // epilogue: +b1, exact GELU, rna-round, write hidden in fragment layout
#pragma unroll
    for (int mi = 0; mi < 4; mi++) {
#pragma unroll
        for (int h2 = 0; h2 < 2; h2++) {
            int row = wm * 64 + mi * 16 + g + 8 * h2;
            int ss = mt * BM + row;
            if (ss < me) {
#pragma unroll
                for (int ni = 0; ni < 8; ni++) {
                    int colb = n0 + wn * 64 + ni * 8 + 2 * t;
                    float b0v = b1[e * HID + colb];
                    float b1v = b1[e * HID + colb + 1];
                    float v0 = rnatf(gelu_exact(acc[mi][ni][2 * h2 + 0] + b0v));
                    float v1 = rnatf(gelu_exact(acc[mi][ni][2 * h2 + 1] + b1v));
                    g_hf[frag_off(e, mt, HID / 8, row, colb)]     = v0;
                    g_hf[frag_off(e, mt, HID / 8, row, colb + 1)] = v1;
                }
            }
        }
    }
}

// ---------------- kernel 4: grouped GEMM2 (K-split x4): out[tok] += c * (hf @ w2) ----------------
__global__ __launch_bounds__(256, 1) void ffn2_kernel(
    const float* __restrict__ w2, float* __restrict__ out)
{
    __shared__ float Bs[2 * BSTG];

    const int e  = blockIdx.z >> 2;
    const int sp = blockIdx.z & 3;
    const int me = g_cnt[e];
    const int mt = blockIdx.x;
    if (mt * BM >= me) return;
    const int n0 = blockIdx.y * BN;

    const int tid  = threadIdx.x;
    const int lane = tid & 31;
    const int wid  = tid >> 5;
    const int wm   = wid >> 2;
    const int wn   = wid & 3;
    const int g    = lane >> 2;
    const int t    = lane & 3;

    // A fragment base (uint4 units), k offset = sp*1024 -> ksq0 = sp*128
    const uint4* aF = (const uint4*)g_hf;
    const size_t aBase = (((size_t)(e * 32 + mt) * (HID / 8) + sp * 128) * 8 + wm * 4) * 32 + lane;

    const int bk = tid >> 6;
    const int n4 = (tid & 63) << 2;
    const float* bptr = w2 + (size_t)e * HID * DIM + (size_t)sp * 1024 * DIM + n0 + n4;
    const int bofs = ((tid & 63) >> 1) * 136 + 4 * (tid & 1);

    float acc[4][8][4];
#pragma unroll
    for (int a = 0; a < 4; a++)
#pragma unroll
        for (int b = 0; b < 8; b++)
#pragma unroll
            for (int q = 0; q < 4; q++) acc[a][b][q] = 0.f;

    uint4 afc[2][4], afn[2][4];
    float4 pb[4];

#pragma unroll
    for (int ks = 0; ks < 2; ks++)
#pragma unroll
        for (int mi = 0; mi < 4; mi++)
            afc[ks][mi] = aF[aBase + (size_t)ks * 256 + mi * 32];
#pragma unroll
    for (int i = 0; i < 4; i++)
        pb[i] = *(const float4*)(bptr + (size_t)(bk + 4 * i) * DIM);
#pragma unroll
    for (int i = 0; i < 4; i++) {
        float4 v = make_float4(rnatf(pb[i].x), rnatf(pb[i].y), rnatf(pb[i].z), rnatf(pb[i].w));
        *(float4*)(Bs + bofs + (bk + 4 * i) * 8) = v;
    }
    __syncthreads();

    const int KT = 1024 / BK;   // 64 per split
    for (int kt = 0; kt < KT; kt++) {
        const int cur = (kt & 1) * BSTG;
        const bool more = (kt + 1 < KT);
        if (more) {
#pragma unroll
            for (int ks = 0; ks < 2; ks++)
#pragma unroll
                for (int mi = 0; mi < 4; mi++)
                    afn[ks][mi] = aF[aBase + (size_t)((kt + 1) * 2 + ks) * 256 + mi * 32];
            const float* bp = bptr + (size_t)(kt + 1) * BK * DIM;
#pragma unroll
            for (int i = 0; i < 4; i++)
                pb[i] = *(const float4*)(bp + (size_t)(bk + 4 * i) * DIM);
        }
#pragma unroll
        for (int ks = 0; ks < 2; ks++) {
            const int k0 = ks * 8;
#pragma unroll
            for (int ni = 0; ni < 8; ni++) {
                int G = wn * 8 + ni;
                uint32_t bf[2];
                bf[0] = __float_as_uint(Bs[cur + G * 136 + (k0 + t) * 8 + g]);
                bf[1] = __float_as_uint(Bs[cur + G * 136 + (k0 + t + 4) * 8 + g]);
#pragma unroll
                for (int mi = 0; mi < 4; mi++)
                    mma8v(acc[mi][ni], afc[ks][mi], bf);
            }
        }
        if (more) {
            const int nxt = ((kt + 1) & 1) * BSTG;
#pragma unroll
            for (int i = 0; i < 4; i++) {
                float4 v = make_float4(rnatf(pb[i].x), rnatf(pb[i].y), rnatf(pb[i].z), rnatf(pb[i].w));
                *(float4*)(Bs + nxt + bofs + (bk + 4 * i) * 8) = v;
            }
#pragma unroll
            for (int ks = 0; ks < 2; ks++)
#pragma unroll
                for (int mi = 0; mi < 4; mi++)
                    afc[ks][mi] = afn[ks][mi];
        }
        __syncthreads();
    }

    // epilogue: scaled scatter-add into fused output (split partials just add)
#pragma unroll
    for (int mi = 0; mi < 4; mi++) {
#pragma unroll
        for (int h2 = 0; h2 < 2; h2++) {
            int row = wm * 64 + mi * 16 + g + 8 * h2;
            int ss = mt * BM + row;
            if (ss < me) {
                int tok  = g_idx[e][ss];
                float wc = g_wt[e][ss];
                float* orow = out + (size_t)tok * DIM;
#pragma unroll
                for (int ni = 0; ni < 8; ni++) {
                    int col = n0 + wn * 64 + ni * 8 + 2 * t;
                    atomicAdd(orow + col,     wc * acc[mi][ni][2 * h2 + 0]);
                    atomicAdd(orow + col + 1, wc * acc[mi][ni][2 * h2 + 1]);
                }
            }
        }
    }
}

// ---------------- launch ----------------
extern "C" void kernel_launch(void* const* d_in, const int* in_sizes, int n_in,
                              void* d_out, int out_size)
{
    (void)in_sizes; (void)n_in; (void)out_size;
    const float* x  = (const float*)d_in[0];
    const float* ei = (const float*)d_in[1];
    const float* wg = (const float*)d_in[2];
    const float* bg = (const float*)d_in[3];
    const float* w1 = (const float*)d_in[4];
    const float* b1 = (const float*)d_in[5];
    const float* w2 = (const float*)d_in[6];
    const float* b2 = (const float*)d_in[7];
    float* out = (float*)d_out;

    gate_kernel<<<NTOK / 8, 256>>>(x, wg, bg, b2, out);
    compact_kernel<<<NEXP, 256>>>();
    permA_kernel<<<dim3(NTOK / BM, NEXP), 256>>>(ei);
    ffn1_kernel<<<dim3(NTOK / BM, HID / BN, NEXP), 256>>>(w1, b1);
    ffn2_kernel<<<dim3(NTOK / BM, DIM / BN, NEXP * 4), 256>>>(w2, out);
}

// round 7
// speedup vs baseline: 1.0063x; 1.0063x over previous
#include <cuda_runtime.h>
#include <cstdint>

#define NTOK 4096
#define DIM  1024
#define NEXP 8
#define HID  4096
#define THR  0.3f

#define BM 128
#define BN 128
#define BK 16
#define BSTG 2176   // floats per B stage (16 * 136)
#define ASTG 2048   // floats per A-frag stage (128 rows * 16 k)

// ---------------- scratch (static device memory; no allocs anywhere) ----------------
__device__ float g_c[NTOK * NEXP];
__device__ int   g_idx[NEXP][NTOK];
__device__ float g_wt[NEXP][NTOK];
__device__ int   g_cnt[NEXP];
// fragment-layout A operands (see frag_off): tiles of 128 rows x 8 k
__device__ __align__(16) float g_af[(size_t)NEXP * NTOK * DIM];   // gathered+rounded expert inputs
__device__ __align__(16) float g_hf[(size_t)NEXP * NTOK * HID];   // gelu hidden, rounded

// ---------------- helpers ----------------
__device__ __forceinline__ uint32_t f2tf(float f) {
    uint32_t u;
    asm("cvt.rna.tf32.f32 %0, %1;" : "=r"(u) : "f"(f));
    return u;
}
__device__ __forceinline__ float rnatf(float f) { return __uint_as_float(f2tf(f)); }

// float-index of element (row r in 128-row tile st, col k) of expert e in fragment layout.
// KQ = K/8 quads. Fragment: [e*32+st][ksq][t16][lane][q] ; lane=((r&7)<<2)|(k&3),
// q = bit3(r) | bit2(k)<<1  -> matches mma.m16n8k8 A-fragment (a0..a3).
__device__ __forceinline__ size_t frag_off(int e, int st, int KQ, int r, int k) {
    size_t blk = (((size_t)(e * 32 + st) * KQ + (k >> 3)) * 8 + (r >> 4)) * 128;
    int lane = ((r & 7) << 2) | (k & 3);
    int q = ((r >> 3) & 1) | (((k >> 2) & 1) << 1);
    return blk + (size_t)(lane << 2) + q;
}

__device__ __forceinline__ void mma8v(float* c, const uint4& a, const uint32_t* b) {
    asm volatile(
        "mma.sync.aligned.m16n8k8.row.col.f32.tf32.tf32.f32 "
        "{%0,%1,%2,%3}, {%4,%5,%6,%7}, {%8,%9}, {%0,%1,%2,%3};"
        : "+f"(c[0]), "+f"(c[1]), "+f"(c[2]), "+f"(c[3])
        : "r"(a.x), "r"(a.y), "r"(a.z), "r"(a.w), "r"(b[0]), "r"(b[1]));
}

__device__ __forceinline__ float gelu_exact(float v) {
    return 0.5f * v * (1.0f + erff(v * 0.70710678118654752f));
}

// ---------------- kernel 1: gate scores, combine weights, out init with sum(c*b2) ----------------
__global__ __launch_bounds__(256) void gate_kernel(
    const float* __restrict__ x, const float* __restrict__ wg,
    const float* __restrict__ bg, const float* __restrict__ b2,
    float* __restrict__ out)
{
    __shared__ float wgs[DIM * 9];
    int tid = threadIdx.x;
    for (int i = tid; i < DIM * NEXP; i += 256)
        wgs[(i >> 3) * 9 + (i & 7)] = wg[i];
    __syncthreads();

    int lane = tid & 31, wid = tid >> 5;
    int n = blockIdx.x * 8 + wid;

    float s[NEXP];
#pragma unroll
    for (int e = 0; e < NEXP; e++) s[e] = 0.f;

    const float* xr = x + (size_t)n * DIM;
    for (int k = lane; k < DIM; k += 32) {
        float xv = xr[k];
#pragma unroll
        for (int e = 0; e < NEXP; e++) s[e] += xv * wgs[k * 9 + e];
    }
#pragma unroll
    for (int e = 0; e < NEXP; e++)
#pragma unroll
        for (int o = 16; o; o >>= 1)
            s[e] += __shfl_xor_sync(0xffffffffu, s[e], o);

    float mx = -1e30f;
#pragma unroll
    for (int e = 0; e < NEXP; e++) { s[e] += bg[e]; mx = fmaxf(mx, s[e]); }
    float sum = 0.f;
#pragma unroll
    for (int e = 0; e < NEXP; e++) { s[e] = expf(s[e] - mx); sum += s[e]; }
    float inv = 1.f / sum;
#pragma unroll
    for (int e = 0; e < NEXP; e++) s[e] *= inv;

    if (lane == 0) {
        float* gs = out + (size_t)NTOK * DIM + (size_t)n * NEXP;
#pragma unroll
        for (int e = 0; e < NEXP; e++) gs[e] = s[e];
    }

    float msum = 0.f; int cnt = 0;
#pragma unroll
    for (int e = 0; e < NEXP; e++) if (s[e] >= THR) { msum += s[e]; cnt++; }
    int top1 = 0; float best = s[0];
#pragma unroll
    for (int e = 1; e < NEXP; e++) if (s[e] > best) { best = s[e]; top1 = e; }
    float dn = 1.f / (msum + 1e-6f);
    float c[NEXP];
#pragma unroll
    for (int e = 0; e < NEXP; e++)
        c[e] = cnt ? ((s[e] >= THR) ? s[e] * dn : 0.f) : ((e == top1) ? 1.f : 0.f);

    if (lane == 0) {
#pragma unroll
        for (int e = 0; e < NEXP; e++) g_c[n * NEXP + e] = c[e];
    }

    for (int d = lane; d < DIM; d += 32) {
        float a = 0.f;
#pragma unroll
        for (int e = 0; e < NEXP; e++) a += c[e] * b2[e * DIM + d];
        out[(size_t)n * DIM + d] = a;
    }
}

// ---------------- kernel 2: per-expert compaction, 1 CTA per expert ----------------
__global__ __launch_bounds__(256) void compact_kernel()
{
    const int e = blockIdx.x;
    __shared__ int wsum[8];
    __shared__ int wbase[9];
    const int tid = threadIdx.x, lane = tid & 31, wid = tid >> 5;

    int base = 0;
#pragma unroll
    for (int c0 = 0; c0 < NTOK; c0 += 256) {
        int n = c0 + tid;
        float c = g_c[n * NEXP + e];
        unsigned m = __ballot_sync(0xffffffffu, c > 0.f);
        if (lane == 0) wsum[wid] = __popc(m);
        __syncthreads();
        if (tid == 0) {
            int acc = 0;
#pragma unroll
            for (int w = 0; w < 8; w++) { wbase[w] = acc; acc += wsum[w]; }
            wbase[8] = acc;
        }
        __syncthreads();
        if (c > 0.f) {
            int pos = base + wbase[wid] + __popc(m & ((1u << lane) - 1u));
            g_idx[e][pos] = n;
            g_wt[e][pos]  = c;
        }
        base += wbase[8];
        __syncthreads();
    }
    if (tid == 0) g_cnt[e] = base;
}

// ---------------- kernel 2b: gather + tf32-round expert inputs into fragment layout ----------------
__global__ __launch_bounds__(256) void permA_kernel(const float* __restrict__ ei)
{
    const int st = blockIdx.x;
    const int e  = blockIdx.y;
    const int me = g_cnt[e];
    if (st * BM >= me) return;
    const int tid  = threadIdx.x;
    const int r    = tid >> 1;          // 0..127 row in tile
    const int half = tid & 1;           // 0..1: k halves of 512
    const int ss = st * BM + r;
    if (ss >= me) return;
    const int tok = g_idx[e][ss];
    const float4* src = (const float4*)(ei + ((size_t)e * NTOK + tok) * DIM) + half * 128;

#pragma unroll 4
    for (int kq = 0; kq < 128; kq++) {
        int k = half * 512 + kq * 4;
        float4 v = src[kq];
        size_t o = frag_off(e, st, DIM / 8, r, k);
        g_af[o +  0] = rnatf(v.x);
        g_af[o +  4] = rnatf(v.y);
        g_af[o +  8] = rnatf(v.z);
        g_af[o + 12] = rnatf(v.w);
    }
}

// =====================================================================================
// FFN GEMMs: 4 warps/CTA (2 wm x 2 wn of 64x64 tiles), CTA tile 128x128, BK=16.
// A: wn==0 warps LDG fragment tiles once and relay via double-buffered smem (LDS.128
//    for all warps) -> A L2 traffic halved. B: double-buffered smem as before.
// =====================================================================================

// ---------------- kernel 3: grouped GEMM1: hf = frag(gelu(A @ w1 + b1)) ----------------
__global__ __launch_bounds__(128, 2) void ffn1_kernel(
    const float* __restrict__ w1, const float* __restrict__ b1)
{
    __shared__ float Bs[2 * BSTG];
    __shared__ __align__(16) float Afs[2 * ASTG];

    const int e  = blockIdx.z;
    const int me = g_cnt[e];
    const int mt = blockIdx.x;
    if (mt * BM >= me) return;
    const int n0 = blockIdx.y * BN;

    const int tid  = threadIdx.x;
    const int lane = tid & 31;
    const int wid  = tid >> 5;
    const int wm   = wid >> 1;     // 0..1
    const int wn   = wid & 1;      // 0..1
    const int g    = lane >> 2;
    const int t    = lane & 3;

    // A fragment global base (uint4 units) — producers (wn==0) only
    const uint4* aF = (const uint4*)g_af;
    const size_t aBase = (((size_t)(e * 32 + mt) * (DIM / 8)) * 8 + wm * 4) * 32 + lane;

    // A-frag smem: [buf][ks(2)][tt(8)][lane(32)] uint4
    uint4* AfsV = (uint4*)Afs;
    const int aSts = (wm * 4) * 32 + lane;          // producer: tiles wm*4..wm*4+3
    const int aLds = (wm * 4) * 32 + lane;          // consumer: same tiles

    // B loader
    const int bk4 = wid * 4;
    const float* bptr = w1 + (size_t)e * DIM * HID + n0 + lane * 4;
    const int bofs = (lane >> 1) * 136 + 4 * (lane & 1);

    float acc[4][8][4];
#pragma unroll
    for (int a = 0; a < 4; a++)
#pragma unroll
        for (int b = 0; b < 8; b++)
#pragma unroll
            for (int q = 0; q < 4; q++) acc[a][b][q] = 0.f;

    uint4 afn[2][4];       // producer prefetch registers
    float4 pb[4];

    // prime stage 0
    if (wn == 0) {
#pragma unroll
        for (int ks = 0; ks < 2; ks++)
#pragma unroll
            for (int mi = 0; mi < 4; mi++)
                AfsV[(ks * 8) * 32 + aSts + mi * 32] = aF[aBase + (size_t)ks * 256 + mi * 32];
    }
#pragma unroll
    for (int i = 0; i < 4; i++)
        pb[i] = *(const float4*)(bptr + (size_t)(bk4 + i) * HID);
#pragma unroll
    for (int i = 0; i < 4; i++) {
        float4 v = make_float4(rnatf(pb[i].x), rnatf(pb[i].y), rnatf(pb[i].z), rnatf(pb[i].w));
        *(float4*)(Bs + bofs + (bk4 + i) * 8) = v;
    }
    __syncthreads();

    const int KT = DIM / BK;   // 64
    for (int kt = 0; kt < KT; kt++) {
        const int curB = (kt & 1) * BSTG;
        const int curA = (kt & 1) * (ASTG / 4);   // uint4 units
        const bool more = (kt + 1 < KT);
        if (more) {
            if (wn == 0) {
#pragma unroll
                for (int ks = 0; ks < 2; ks++)
#pragma unroll
                    for (int mi = 0; mi < 4; mi++)
                        afn[ks][mi] = aF[aBase + (size_t)((kt + 1) * 2 + ks) * 256 + mi * 32];
            }
            const float* bp = bptr + (size_t)(kt + 1) * BK * HID;
#pragma unroll
            for (int i = 0; i < 4; i++)
                pb[i] = *(const float4*)(bp + (size_t)(bk4 + i) * HID);
        }
#pragma unroll
        for (int ks = 0; ks < 2; ks++) {
            const int k0 = ks * 8;
            uint4 afc[4];
#pragma unroll
            for (int mi = 0; mi < 4; mi++)
                afc[mi] = AfsV[curA + (ks * 8) * 32 + aLds + mi * 32];
#pragma unroll
            for (int ni = 0; ni < 8; ni++) {
                int G = wn * 8 + ni;
                uint32_t bf[2];
                bf[0] = __float_as_uint(Bs[curB + G * 136 + (k0 + t) * 8 + g]);
                bf[1] = __float_as_uint(Bs[curB + G * 136 + (k0 + t + 4) * 8 + g]);
#pragma unroll
                for (int mi = 0; mi < 4; mi++)
                    mma8v(acc[mi][ni], afc[mi], bf);
            }
        }
        if (more) {
            const int nxtB = ((kt + 1) & 1) * BSTG;
            const int nxtA = ((kt + 1) & 1) * (ASTG / 4);
#pragma unroll
            for (int i = 0; i < 4; i++) {
                float4 v = make_float4(rnatf(pb[i].x), rnatf(pb[i].y), rnatf(pb[i].z), rnatf(pb[i].w));
                *(float4*)(Bs + nxtB + bofs + (bk4 + i) * 8) = v;
            }
            if (wn == 0) {
#pragma unroll
                for (int ks = 0; ks < 2; ks++)
#pragma unroll
                    for (int mi = 0; mi < 4; mi++)
                        AfsV[nxtA + (ks * 8) * 32 + aSts + mi * 32] = afn[ks][mi];
            }
        }
        __syncthreads();
    }

    // epilogue: +b1, exact GELU, rna-round, write hidden in fragment layout
#pragma unroll
    for (int mi = 0; mi < 4; mi++) {
#pragma unroll
        for (int h2 = 0; h2 < 2; h2++) {
            int row = wm * 64 + mi * 16 + g + 8 * h2;
            int ss = mt * BM + row;
            if (ss < me) {
#pragma unroll
                for (int ni = 0; ni < 8; ni++) {
                    int colb = n0 + wn * 64 + ni * 8 + 2 * t;
                    float b0v = b1[e * HID + colb];
                    float b1v = b1[e * HID + colb + 1];
                    float v0 = rnatf(gelu_exact(acc[mi][ni][2 * h2 + 0] + b0v));
                    float v1 = rnatf(gelu_exact(acc[mi][ni][2 * h2 + 1] + b1v));
                    g_hf[frag_off(e, mt, HID / 8, row, colb)]     = v0;
                    g_hf[frag_off(e, mt, HID / 8, row, colb + 1)] = v1;
                }
            }
        }
    }
}

// ---------------- kernel 4: grouped GEMM2 (K-split x4): out[tok] += c * (hf @ w2) ----------------
__global__ __launch_bounds__(128, 2) void ffn2_kernel(
    const float* __restrict__ w2, float* __restrict__ out)
{
    __shared__ float Bs[2 * BSTG];
    __shared__ __align__(16) float Afs[2 * ASTG];

    const int e  = blockIdx.z >> 2;
    const int sp = blockIdx.z & 3;
    const int me = g_cnt[e];
    const int mt = blockIdx.x;
    if (mt * BM >= me) return;
    const int n0 = blockIdx.y * BN;

    const int tid  = threadIdx.x;
    const int lane = tid & 31;
    const int wid  = tid >> 5;
    const int wm   = wid >> 1;
    const int wn   = wid & 1;
    const int g    = lane >> 2;
    const int t    = lane & 3;

    const uint4* aF = (const uint4*)g_hf;
    const size_t aBase = (((size_t)(e * 32 + mt) * (HID / 8) + sp * 128) * 8 + wm * 4) * 32 + lane;

    uint4* AfsV = (uint4*)Afs;
    const int aSts = (wm * 4) * 32 + lane;
    const int aLds = (wm * 4) * 32 + lane;

    const int bk4 = wid * 4;
    const float* bptr = w2 + (size_t)e * HID * DIM + (size_t)sp * 1024 * DIM + n0 + lane * 4;
    const int bofs = (lane >> 1) * 136 + 4 * (lane & 1);

    float acc[4][8][4];
#pragma unroll
    for (int a = 0; a < 4; a++)
#pragma unroll
        for (int b = 0; b < 8; b++)
#pragma unroll
            for (int q = 0; q < 4; q++) acc[a][b][q] = 0.f;

    uint4 afn[2][4];
    float4 pb[4];

    if (wn == 0) {
#pragma unroll
        for (int ks = 0; ks < 2; ks++)
#pragma unroll
            for (int mi = 0; mi < 4; mi++)
                AfsV[(ks * 8) * 32 + aSts + mi * 32] = aF[aBase + (size_t)ks * 256 + mi * 32];
    }
#pragma unroll
    for (int i = 0; i < 4; i++)
        pb[i] = *(const float4*)(bptr + (size_t)(bk4 + i) * DIM);
#pragma unroll
    for (int i = 0; i < 4; i++) {
        float4 v = make_float4(rnatf(pb[i].x), rnatf(pb[i].y), rnatf(pb[i].z), rnatf(pb[i].w));
        *(float4*)(Bs + bofs + (bk4 + i) * 8) = v;
    }
    __syncthreads();

    const int KT = 1024 / BK;   // 64 per split
    for (int kt = 0; kt < KT; kt++) {
        const int curB = (kt & 1) * BSTG;
        const int curA = (kt & 1) * (ASTG / 4);
        const bool more = (kt + 1 < KT);
        if (more) {
            if (wn == 0) {
#pragma unroll
                for (int ks = 0; ks < 2; ks++)
#pragma unroll
                    for (int mi = 0; mi < 4; mi++)
                        afn[ks][mi] = aF[aBase + (size_t)((kt + 1) * 2 + ks) * 256 + mi * 32];
            }
            const float* bp = bptr + (size_t)(kt + 1) * BK * DIM;
#pragma unroll
            for (int i = 0; i < 4; i++)
                pb[i] = *(const float4*)(bp + (size_t)(bk4 + i) * DIM);
        }
#pragma unroll
        for (int ks = 0; ks < 2; ks++) {
            const int k0 = ks * 8;
            uint4 afc[4];
#pragma unroll
            for (int mi = 0; mi < 4; mi++)
                afc[mi] = AfsV[curA + (ks * 8) * 32 + aLds + mi * 32];
#pragma unroll
            for (int ni = 0; ni < 8; ni++) {
                int G = wn * 8 + ni;
                uint32_t bf[2];
                bf[0] = __float_as_uint(Bs[curB + G * 136 + (k0 + t) * 8 + g]);
                bf[1] = __float_as_uint(Bs[curB + G * 136 + (k0 + t + 4) * 8 + g]);
#pragma unroll
                for (int mi = 0; mi < 4; mi++)
                    mma8v(acc[mi][ni], afc[mi], bf);
            }
        }
        if (more) {
            const int nxtB = ((kt + 1) & 1) * BSTG;
            const int nxtA = ((kt + 1) & 1) * (ASTG / 4);
#pragma unroll
            for (int i = 0; i < 4; i++) {
                float4 v = make_float4(rnatf(pb[i].x), rnatf(pb[i].y), rnatf(pb[i].z), rnatf(pb[i].w));
                *(float4*)(Bs + nxtB + bofs + (bk4 + i) * 8) = v;
            }
            if (wn == 0) {
#pragma unroll
                for (int ks = 0; ks < 2; ks++)
#pragma unroll
                    for (int mi = 0; mi < 4; mi++)
                        AfsV[nxtA + (ks * 8) * 32 + aSts + mi * 32] = afn[ks][mi];
            }
        }
        __syncthreads();
    }

    // epilogue: scaled scatter-add into fused output (split partials just add)
#pragma unroll
    for (int mi = 0; mi < 4; mi++) {
#pragma unroll
        for (int h2 = 0; h2 < 2; h2++) {
            int row = wm * 64 + mi * 16 + g + 8 * h2;
            int ss = mt * BM + row;
            if (ss < me) {
                int tok  = g_idx[e][ss];
                float wc = g_wt[e][ss];
                float* orow = out + (size_t)tok * DIM;
#pragma unroll
                for (int ni = 0; ni < 8; ni++) {
                    int col = n0 + wn * 64 + ni * 8 + 2 * t;
                    atomicAdd(orow + col,     wc * acc[mi][ni][2 * h2 + 0]);
                    atomicAdd(orow + col + 1, wc * acc[mi][ni][2 * h2 + 1]);
                }
            }
        }
    }
}

// ---------------- launch ----------------
extern "C" void kernel_launch(void* const* d_in, const int* in_sizes, int n_in,
                              void* d_out, int out_size)
{
    (void)in_sizes; (void)n_in; (void)out_size;
    const float* x  = (const float*)d_in[0];
    const float* ei = (const float*)d_in[1];
    const float* wg = (const float*)d_in[2];
    const float* bg = (const float*)d_in[3];
    const float* w1 = (const float*)d_in[4];
    const float* b1 = (const float*)d_in[5];
    const float* w2 = (const float*)d_in[6];
    const float* b2 = (const float*)d_in[7];
    float* out = (float*)d_out;

    gate_kernel<<<NTOK / 8, 256>>>(x, wg, bg, b2, out);
    compact_kernel<<<NEXP, 256>>>();
    permA_kernel<<<dim3(NTOK / BM, NEXP), 256>>>(ei);
    ffn1_kernel<<<dim3(NTOK / BM, HID / BN, NEXP), 128>>>(w1, b1);
    ffn2_kernel<<<dim3(NTOK / BM, DIM / BN, NEXP * 4), 128>>>(w2, out);
}

// round 8
// speedup vs baseline: 1.3156x; 1.3073x over previous
#include <cuda_runtime.h>
#include <cuda_fp16.h>
#include <cstdint>

#define NTOK 4096
#define DIM  1024
#define NEXP 8
#define HID  4096
#define THR  0.3f

#define BM 128
#define BN 128
#define BST 544    // uint2 (half2-pairs) per B stage: 16 G-groups * 34

// ---------------- scratch (static device memory; no allocs anywhere) ----------------
__device__ float g_c[NTOK * NEXP];
__device__ int   g_idx[NEXP][NTOK];
__device__ float g_wt[NEXP][NTOK];
__device__ int   g_cnt[NEXP];
// fp16 A operands in m16n8k16 fragment layout (one uint4 per lane per 16-row x 16-k block)
__device__ __align__(16) uint32_t g_af[(size_t)NEXP * NTOK * DIM / 2];   // half2 units
__device__ __align__(16) uint32_t g_hf[(size_t)NEXP * NTOK * HID / 2];   // half2 units

// ---------------- helpers ----------------
// pack2(lo, hi): f16x2 with lo in low half (cvt.rn = round-nearest-even)
__device__ __forceinline__ uint32_t pack2(float lo, float hi) {
    uint32_t r;
    asm("cvt.rn.f16x2.f32 %0, %1, %2;" : "=r"(r) : "f"(hi), "f"(lo));
    return r;
}

__device__ __forceinline__ void mma16(float* c, const uint4& a, const uint2& b) {
    asm volatile(
        "mma.sync.aligned.m16n8k16.row.col.f32.f16.f16.f32 "
        "{%0,%1,%2,%3}, {%4,%5,%6,%7}, {%8,%9}, {%0,%1,%2,%3};"
        : "+f"(c[0]), "+f"(c[1]), "+f"(c[2]), "+f"(c[3])
        : "r"(a.x), "r"(a.y), "r"(a.z), "r"(a.w), "r"(b.x), "r"(b.y));
}

__device__ __forceinline__ float gelu_exact(float v) {
    return 0.5f * v * (1.0f + erff(v * 0.70710678118654752f));
}

// ---------------- kernel 1: gate scores, combine weights, out init with sum(c*b2) ----------------
__global__ __launch_bounds__(256) void gate_kernel(
    const float* __restrict__ x, const float* __restrict__ wg,
    const float* __restrict__ bg, const float* __restrict__ b2,
    float* __restrict__ out)
{
    __shared__ float wgs[DIM * 9];
    int tid = threadIdx.x;
    for (int i = tid; i < DIM * NEXP; i += 256)
        wgs[(i >> 3) * 9 + (i & 7)] = wg[i];
    __syncthreads();

    int lane = tid & 31, wid = tid >> 5;
    int n = blockIdx.x * 8 + wid;

    float s[NEXP];
#pragma unroll
    for (int e = 0; e < NEXP; e++) s[e] = 0.f;

    const float* xr = x + (size_t)n * DIM;
    for (int k = lane; k < DIM; k += 32) {
        float xv = xr[k];
#pragma unroll
        for (int e = 0; e < NEXP; e++) s[e] += xv * wgs[k * 9 + e];
    }
#pragma unroll
    for (int e = 0; e < NEXP; e++)
#pragma unroll
        for (int o = 16; o; o >>= 1)
            s[e] += __shfl_xor_sync(0xffffffffu, s[e], o);

    float mx = -1e30f;
#pragma unroll
    for (int e = 0; e < NEXP; e++) { s[e] += bg[e]; mx = fmaxf(mx, s[e]); }
    float sum = 0.f;
#pragma unroll
    for (int e = 0; e < NEXP; e++) { s[e] = expf(s[e] - mx); sum += s[e]; }
    float inv = 1.f / sum;
#pragma unroll
    for (int e = 0; e < NEXP; e++) s[e] *= inv;

    if (lane == 0) {
        float* gs = out + (size_t)NTOK * DIM + (size_t)n * NEXP;
#pragma unroll
        for (int e = 0; e < NEXP; e++) gs[e] = s[e];
    }

    float msum = 0.f; int cnt = 0;
#pragma unroll
    for (int e = 0; e < NEXP; e++) if (s[e] >= THR) { msum += s[e]; cnt++; }
    int top1 = 0; float best = s[0];
#pragma unroll
    for (int e = 1; e < NEXP; e++) if (s[e] > best) { best = s[e]; top1 = e; }
    float dn = 1.f / (msum + 1e-6f);
    float c[NEXP];
#pragma unroll
    for (int e = 0; e < NEXP; e++)
        c[e] = cnt ? ((s[e] >= THR) ? s[e] * dn : 0.f) : ((e == top1) ? 1.f : 0.f);

    if (lane == 0) {
#pragma unroll
        for (int e = 0; e < NEXP; e++) g_c[n * NEXP + e] = c[e];
    }

    for (int d = lane; d < DIM; d += 32) {
        float a = 0.f;
#pragma unroll
        for (int e = 0; e < NEXP; e++) a += c[e] * b2[e * DIM + d];
        out[(size_t)n * DIM + d] = a;
    }
}

// ---------------- kernel 2: per-expert compaction, 1 CTA per expert ----------------
__global__ __launch_bounds__(256) void compact_kernel()
{
    const int e = blockIdx.x;
    __shared__ int wsum[8];
    __shared__ int wbase[9];
    const int tid = threadIdx.x, lane = tid & 31, wid = tid >> 5;

    int base = 0;
#pragma unroll
    for (int c0 = 0; c0 < NTOK; c0 += 256) {
        int n = c0 + tid;
        float c = g_c[n * NEXP + e];
        unsigned m = __ballot_sync(0xffffffffu, c > 0.f);
        if (lane == 0) wsum[wid] = __popc(m);
        __syncthreads();
        if (tid == 0) {
            int acc = 0;
#pragma unroll
            for (int w = 0; w < 8; w++) { wbase[w] = acc; acc += wsum[w]; }
            wbase[8] = acc;
        }
        __syncthreads();
        if (c > 0.f) {
            int pos = base + wbase[wid] + __popc(m & ((1u << lane) - 1u));
            g_idx[e][pos] = n;
            g_wt[e][pos]  = c;
        }
        base += wbase[8];
        __syncthreads();
    }
    if (tid == 0) g_cnt[e] = base;
}

// ---------------- kernel 2b: gather + fp16-round expert inputs into fragment layout ----------------
__global__ __launch_bounds__(256) void permA_kernel(const float* __restrict__ ei)
{
    const int st = blockIdx.x;
    const int e  = blockIdx.y;
    const int me = g_cnt[e];
    if (st * BM >= me) return;
    const int tid = threadIdx.x;
    uint4* dst = (uint4*)g_af;

#pragma unroll 2
    for (int i = 0; i < 64; i++) {
        int idx  = i * 256 + tid;
        int lane = idx & 31;
        int kq   = (idx >> 5) & 63;          // DIM/16 = 64
        int rr   = idx >> 11;                // 0..7
        int g = lane >> 2, t = lane & 3;
        int r = rr * 16 + g;
        int s0 = st * BM + r, s1 = s0 + 8;
        int tok0 = (s0 < me) ? g_idx[e][s0] : 0;
        int tok1 = (s1 < me) ? g_idx[e][s1] : 0;
        const float2* r0 = (const float2*)(ei + ((size_t)e * NTOK + tok0) * DIM);
        const float2* r1 = (const float2*)(ei + ((size_t)e * NTOK + tok1) * DIM);
        float2 a00 = r0[kq * 8 + t];
        float2 a01 = r0[kq * 8 + t + 4];
        float2 a10 = r1[kq * 8 + t];
        float2 a11 = r1[kq * 8 + t + 4];
        uint4 v;
        v.x = pack2(a00.x, a00.y);   // (r,   klo)
        v.y = pack2(a10.x, a10.y);   // (r+8, klo)
        v.z = pack2(a01.x, a01.y);   // (r,   khi)
        v.w = pack2(a11.x, a11.y);   // (r+8, khi)
        dst[(((size_t)(e * 32 + st) * 64 + kq) * 8 + rr) * 32 + lane] = v;
    }
}

// =====================================================================================
// FFN GEMMs: 4 warps/CTA (2 wm x 2 wn of 64x64 tiles), CTA 128x128, k-step 16, fp16 MMA.
// A: one LDG.128 per (mi,kt) from fragment-layout global. B: double-buffered smem,
//    stored as {b0,b1} half2-pairs -> 1 LDS.64 per ni, conflict-free both directions.
// =====================================================================================

// ---------------- kernel 3: grouped GEMM1: g_hf = frag16(gelu(A @ w1 + b1)) ----------------
__global__ __launch_bounds__(128, 2) void ffn1_kernel(
    const float* __restrict__ w1, const float* __restrict__ b1)
{
    __shared__ uint2 Bs[2 * BST];

    const int e  = blockIdx.z;
    const int me = g_cnt[e];
    const int mt = blockIdx.x;
    if (mt * BM >= me) return;
    const int n0 = blockIdx.y * BN;

    const int tid  = threadIdx.x;
    const int lane = tid & 31;
    const int wid  = tid >> 5;
    const int wm   = wid >> 1;
    const int wn   = wid & 1;
    const int g    = lane >> 2;
    const int t    = lane & 3;

    // A fragments (uint4 units)
    const uint4* aF = (const uint4*)g_af;
    const size_t aB = (size_t)(e * 32 + mt) * 64 * 256 + (wm * 4) * 32 + lane;

    // B producer: thread covers rows kt*16 + wid*2 + {0,1,8,9}, col quad lane*4
    const float* bp0 = w1 + (size_t)e * DIM * HID + n0 + lane * 4;
    const int Gp = lane >> 1, gb = (lane & 1) * 4;
    const int stsBase = Gp * 34 + gb * 4 + wid;   // uint2 units; +4 per col j

    float acc[4][8][4];
#pragma unroll
    for (int a = 0; a < 4; a++)
#pragma unroll
        for (int b = 0; b < 8; b++)
#pragma unroll
            for (int q = 0; q < 4; q++) acc[a][b][q] = 0.f;

    uint4 afc[4], afn[4];
    float4 pb[4];

    // prime stage 0
#pragma unroll
    for (int mi = 0; mi < 4; mi++) afc[mi] = aF[aB + mi * 32];
#pragma unroll
    for (int i = 0; i < 4; i++) {
        int kd = wid * 2 + (i & 1) + (i >> 1) * 8;   // {0,1,8,9} offsets
        pb[i] = *(const float4*)(bp0 + (size_t)kd * HID);
    }
    {
        Bs[stsBase +  0] = make_uint2(pack2(pb[0].x, pb[1].x), pack2(pb[2].x, pb[3].x));
        Bs[stsBase +  4] = make_uint2(pack2(pb[0].y, pb[1].y), pack2(pb[2].y, pb[3].y));
        Bs[stsBase +  8] = make_uint2(pack2(pb[0].z, pb[1].z), pack2(pb[2].z, pb[3].z));
        Bs[stsBase + 12] = make_uint2(pack2(pb[0].w, pb[1].w), pack2(pb[2].w, pb[3].w));
    }
    __syncthreads();

    const int KT = DIM / 16;   // 64
    for (int kt = 0; kt < KT; kt++) {
        const int cur = (kt & 1) * BST;
        const bool more = (kt + 1 < KT);
        if (more) {
#pragma unroll
            for (int mi = 0; mi < 4; mi++)
                afn[mi] = aF[aB + (size_t)(kt + 1) * 256 + mi * 32];
            const float* bp = bp0 + (size_t)(kt + 1) * 16 * HID;
#pragma unroll
            for (int i = 0; i < 4; i++) {
                int kd = wid * 2 + (i & 1) + (i >> 1) * 8;
                pb[i] = *(const float4*)(bp + (size_t)kd * HID);
            }
        }
#pragma unroll
        for (int ni = 0; ni < 8; ni++) {
            uint2 bf = Bs[cur + (wn * 8 + ni) * 34 + g * 4 + t];
#pragma unroll
            for (int mi = 0; mi < 4; mi++)
                mma16(acc[mi][ni], afc[mi], bf);
        }
        if (more) {
            const int nxt = ((kt + 1) & 1) * BST;
            Bs[nxt + stsBase +  0] = make_uint2(pack2(pb[0].x, pb[1].x), pack2(pb[2].x, pb[3].x));
            Bs[nxt + stsBase +  4] = make_uint2(pack2(pb[0].y, pb[1].y), pack2(pb[2].y, pb[3].y));
            Bs[nxt + stsBase +  8] = make_uint2(pack2(pb[0].z, pb[1].z), pack2(pb[2].z, pb[3].z));
            Bs[nxt + stsBase + 12] = make_uint2(pack2(pb[0].w, pb[1].w), pack2(pb[2].w, pb[3].w));
#pragma unroll
            for (int mi = 0; mi < 4; mi++) afc[mi] = afn[mi];
        }
        __syncthreads();
    }

    // epilogue: +b1, exact GELU, pack to fp16 fragment layout for GEMM2 (coalesced STG.128)
    float bv[8][2];
#pragma unroll
    for (int ni = 0; ni < 8; ni++) {
        int c = n0 + wn * 64 + ni * 8 + 2 * t;
        bv[ni][0] = b1[e * HID + c];
        bv[ni][1] = b1[e * HID + c + 1];
    }
    uint4* hf = (uint4*)g_hf;
#pragma unroll
    for (int mi = 0; mi < 4; mi++) {
#pragma unroll
        for (int p = 0; p < 4; p++) {
            int n0i = 2 * p, n1i = 2 * p + 1;
            uint4 v;
            v.x = pack2(gelu_exact(acc[mi][n0i][0] + bv[n0i][0]),
                        gelu_exact(acc[mi][n0i][1] + bv[n0i][1]));
            v.y = pack2(gelu_exact(acc[mi][n0i][2] + bv[n0i][0]),
                        gelu_exact(acc[mi][n0i][3] + bv[n0i][1]));
            v.z = pack2(gelu_exact(acc[mi][n1i][0] + bv[n1i][0]),
                        gelu_exact(acc[mi][n1i][1] + bv[n1i][1]));
            v.w = pack2(gelu_exact(acc[mi][n1i][2] + bv[n1i][0]),
                        gelu_exact(acc[mi][n1i][3] + bv[n1i][1]));
            int kq = (n0 >> 4) + wn * 4 + p;
            hf[(((size_t)(e * 32 + mt) * 256 + kq) * 8 + (wm * 4 + mi)) * 32 + lane] = v;
        }
    }
}

// ---------------- kernel 4: grouped GEMM2 (K-split x4): out[tok] += c * (g_hf @ w2) ----------------
__global__ __launch_bounds__(128, 2) void ffn2_kernel(
    const float* __restrict__ w2, float* __restrict__ out)
{
    __shared__ uint2 Bs[2 * BST];

    const int e  = blockIdx.z >> 2;
    const int sp = blockIdx.z & 3;
    const int me = g_cnt[e];
    const int mt = blockIdx.x;
    if (mt * BM >= me) return;
    const int n0 = blockIdx.y * BN;

    const int tid  = threadIdx.x;
    const int lane = tid & 31;
    const int wid  = tid >> 5;
    const int wm   = wid >> 1;
    const int wn   = wid & 1;
    const int g    = lane >> 2;
    const int t    = lane & 3;

    const uint4* aF = (const uint4*)g_hf;
    const size_t aB = ((size_t)(e * 32 + mt) * 256 + sp * 64) * 256 + (wm * 4) * 32 + lane;

    const float* bp0 = w2 + (size_t)e * HID * DIM + (size_t)sp * 1024 * DIM + n0 + lane * 4;
    const int Gp = lane >> 1, gb = (lane & 1) * 4;
    const int stsBase = Gp * 34 + gb * 4 + wid;

    float acc[4][8][4];
#pragma unroll
    for (int a = 0; a < 4; a++)
#pragma unroll
        for (int b = 0; b < 8; b++)
#pragma unroll
            for (int q = 0; q < 4; q++) acc[a][b][q] = 0.f;

    uint4 afc[4], afn[4];
    float4 pb[4];

#pragma unroll
    for (int mi = 0; mi < 4; mi++) afc[mi] = aF[aB + mi * 32];
#pragma unroll
    for (int i = 0; i < 4; i++) {
        int kd = wid * 2 + (i & 1) + (i >> 1) * 8;
        pb[i] = *(const float4*)(bp0 + (size_t)kd * DIM);
    }
    {
        Bs[stsBase +  0] = make_uint2(pack2(pb[0].x, pb[1].x), pack2(pb[2].x, pb[3].x));
        Bs[stsBase +  4] = make_uint2(pack2(pb[0].y, pb[1].y), pack2(pb[2].y, pb[3].y));
        Bs[stsBase +  8] = make_uint2(pack2(pb[0].z, pb[1].z), pack2(pb[2].z, pb[3].z));
        Bs[stsBase + 12] = make_uint2(pack2(pb[0].w, pb[1].w), pack2(pb[2].w, pb[3].w));
    }
    __syncthreads();

    const int KT = 1024 / 16;   // 64 per split
    for (int kt = 0; kt < KT; kt++) {
        const int cur = (kt & 1) * BST;
        const bool more = (kt + 1 < KT);
        if (more) {
#pragma unroll
            for (int mi = 0; mi < 4; mi++)
                afn[mi] = aF[aB + (size_t)(kt + 1) * 256 + mi * 32];
            const float* bp = bp0 + (size_t)(kt + 1) * 16 * DIM;
#pragma unroll
            for (int i = 0; i < 4; i++) {
                int kd = wid * 2 + (i & 1) + (i >> 1) * 8;
                pb[i] = *(const float4*)(bp + (size_t)kd * DIM);
            }
        }
#pragma unroll
        for (int ni = 0; ni < 8; ni++) {
            uint2 bf = Bs[cur + (wn * 8 + ni) * 34 + g * 4 + t];
#pragma unroll
            for (int mi = 0; mi < 4; mi++)
                mma16(acc[mi][ni], afc[mi], bf);
        }
        if (more) {
            const int nxt = ((kt + 1) & 1) * BST;
            Bs[nxt + stsBase +  0] = make_uint2(pack2(pb[0].x, pb[1].x), pack2(pb[2].x, pb[3].x));
            Bs[nxt + stsBase +  4] = make_uint2(pack2(pb[0].y, pb[1].y), pack2(pb[2].y, pb[3].y));
            Bs[nxt + stsBase +  8] = make_uint2(pack2(pb[0].z, pb[1].z), pack2(pb[2].z, pb[3].z));
            Bs[nxt + stsBase + 12] = make_uint2(pack2(pb[0].w, pb[1].w), pack2(pb[2].w, pb[3].w));
#pragma unroll
            for (int mi = 0; mi < 4; mi++) afc[mi] = afn[mi];
        }
        __syncthreads();
    }

    // epilogue: scaled scatter-add into fused output (split partials just add)
#pragma unroll
    for (int mi = 0; mi < 4; mi++) {
#pragma unroll
        for (int h2 = 0; h2 < 2; h2++) {
            int row = wm * 64 + mi * 16 + g + 8 * h2;
            int ss = mt * BM + row;
            if (ss < me) {
                int tok  = g_idx[e][ss];
                float wc = g_wt[e][ss];
                float* orow = out + (size_t)tok * DIM;
#pragma unroll
                for (int ni = 0; ni < 8; ni++) {
                    int col = n0 + wn * 64 + ni * 8 + 2 * t;
                    atomicAdd(orow + col,     wc * acc[mi][ni][2 * h2 + 0]);
                    atomicAdd(orow + col + 1, wc * acc[mi][ni][2 * h2 + 1]);
                }
            }
        }
    }
}

// ---------------- launch ----------------
extern "C" void kernel_launch(void* const* d_in, const int* in_sizes, int n_in,
                              void* d_out, int out_size)
{
    (void)in_sizes; (void)n_in; (void)out_size;
    const float* x  = (const float*)d_in[0];
    const float* ei = (const float*)d_in[1];
    const float* wg = (const float*)d_in[2];
    const float* bg = (const float*)d_in[3];
    const float* w1 = (const float*)d_in[4];
    const float* b1 = (const float*)d_in[5];
    const float* w2 = (const float*)d_in[6];
    const float* b2 = (const float*)d_in[7];
    float* out = (float*)d_out;

    gate_kernel<<<NTOK / 8, 256>>>(x, wg, bg, b2, out);
    compact_kernel<<<NEXP, 256>>>();
    permA_kernel<<<dim3(NTOK / BM, NEXP), 256>>>(ei);
    ffn1_kernel<<<dim3(NTOK / BM, HID / BN, NEXP), 128>>>(w1, b1);
    ffn2_kernel<<<dim3(NTOK / BM, DIM / BN, NEXP * 4), 128>>>(w2, out);
}

// round 9
// speedup vs baseline: 1.6310x; 1.2397x over previous
#include <cuda_runtime.h>
#include <cuda_fp16.h>
#include <cstdint>

#define NTOK 4096
#define DIM  1024
#define NEXP 8
#define HID  4096
#define THR  0.3f

#define BM 128
#define BN 128

// ---------------- scratch (static device memory; no allocs anywhere) ----------------
__device__ float g_c[NTOK * NEXP];
__device__ int   g_idx[NEXP][NTOK];
__device__ float g_wt[NEXP][NTOK];
__device__ int   g_cnt[NEXP];
// fp16 A operands in m16n8k16 fragment layout (one uint4 per lane per 16-row x 16-k block)
__device__ __align__(16) uint32_t g_af[(size_t)NEXP * NTOK * DIM / 2];   // half2 units
__device__ __align__(16) uint32_t g_hf[(size_t)NEXP * NTOK * HID / 2];   // half2 units
// fp16 B operands in fragment layout: uint2 per lane per (kt, n-group-of-8)
//   index = (((e*KT + kt)*NG + G)*8 + c8)*4 + k2 ; within (kt,G): offset = lane
__device__ __align__(16) uint2 g_wf1[(size_t)NEXP * (DIM / 16) * (HID / 8) * 32];
__device__ __align__(16) uint2 g_wf2[(size_t)NEXP * (HID / 16) * (DIM / 8) * 32];

// ---------------- helpers ----------------
// pack2(lo, hi): f16x2 with lo in low half (cvt.rn = round-nearest-even)
__device__ __forceinline__ uint32_t pack2(float lo, float hi) {
    uint32_t r;
    asm("cvt.rn.f16x2.f32 %0, %1, %2;" : "=r"(r) : "f"(hi), "f"(lo));
    return r;
}

__device__ __forceinline__ void mma16(float* c, const uint4& a, const uint2& b) {
    asm volatile(
        "mma.sync.aligned.m16n8k16.row.col.f32.f16.f16.f32 "
        "{%0,%1,%2,%3}, {%4,%5,%6,%7}, {%8,%9}, {%0,%1,%2,%3};"
        : "+f"(c[0]), "+f"(c[1]), "+f"(c[2]), "+f"(c[3])
        : "r"(a.x), "r"(a.y), "r"(a.z), "r"(a.w), "r"(b.x), "r"(b.y));
}

__device__ __forceinline__ float gelu_exact(float v) {
    return 0.5f * v * (1.0f + erff(v * 0.70710678118654752f));
}

// ---------------- kernel 1: gate scores, combine weights, out init with sum(c*b2) ----------------
__global__ __launch_bounds__(256) void gate_kernel(
    const float* __restrict__ x, const float* __restrict__ wg,
    const float* __restrict__ bg, const float* __restrict__ b2,
    float* __restrict__ out)
{
    __shared__ float wgs[DIM * 9];
    int tid = threadIdx.x;
    for (int i = tid; i < DIM * NEXP; i += 256)
        wgs[(i >> 3) * 9 + (i & 7)] = wg[i];
    __syncthreads();

    int lane = tid & 31, wid = tid >> 5;
    int n = blockIdx.x * 8 + wid;

    float s[NEXP];
#pragma unroll
    for (int e = 0; e < NEXP; e++) s[e] = 0.f;

    const float* xr = x + (size_t)n * DIM;
    for (int k = lane; k < DIM; k += 32) {
        float xv = xr[k];
#pragma unroll
        for (int e = 0; e < NEXP; e++) s[e] += xv * wgs[k * 9 + e];
    }
#pragma unroll
    for (int e = 0; e < NEXP; e++)
#pragma unroll
        for (int o = 16; o; o >>= 1)
            s[e] += __shfl_xor_sync(0xffffffffu, s[e], o);

    float mx = -1e30f;
#pragma unroll
    for (int e = 0; e < NEXP; e++) { s[e] += bg[e]; mx = fmaxf(mx, s[e]); }
    float sum = 0.f;
#pragma unroll
    for (int e = 0; e < NEXP; e++) { s[e] = expf(s[e] - mx); sum += s[e]; }
    float inv = 1.f / sum;
#pragma unroll
    for (int e = 0; e < NEXP; e++) s[e] *= inv;

    if (lane == 0) {
        float* gs = out + (size_t)NTOK * DIM + (size_t)n * NEXP;
#pragma unroll
        for (int e = 0; e < NEXP; e++) gs[e] = s[e];
    }

    float msum = 0.f; int cnt = 0;
#pragma unroll
    for (int e = 0; e < NEXP; e++) if (s[e] >= THR) { msum += s[e]; cnt++; }
    int top1 = 0; float best = s[0];
#pragma unroll
    for (int e = 1; e < NEXP; e++) if (s[e] > best) { best = s[e]; top1 = e; }
    float dn = 1.f / (msum + 1e-6f);
    float c[NEXP];
#pragma unroll
    for (int e = 0; e < NEXP; e++)
        c[e] = cnt ? ((s[e] >= THR) ? s[e] * dn : 0.f) : ((e == top1) ? 1.f : 0.f);

    if (lane == 0) {
#pragma unroll
        for (int e = 0; e < NEXP; e++) g_c[n * NEXP + e] = c[e];
    }

    for (int d = lane; d < DIM; d += 32) {
        float a = 0.f;
#pragma unroll
        for (int e = 0; e < NEXP; e++) a += c[e] * b2[e * DIM + d];
        out[(size_t)n * DIM + d] = a;
    }
}

// ---------------- kernel 2: per-expert compaction, 1 CTA per expert ----------------
__global__ __launch_bounds__(256) void compact_kernel()
{
    const int e = blockIdx.x;
    __shared__ int wsum[8];
    __shared__ int wbase[9];
    const int tid = threadIdx.x, lane = tid & 31, wid = tid >> 5;

    int base = 0;
#pragma unroll
    for (int c0 = 0; c0 < NTOK; c0 += 256) {
        int n = c0 + tid;
        float c = g_c[n * NEXP + e];
        unsigned m = __ballot_sync(0xffffffffu, c > 0.f);
        if (lane == 0) wsum[wid] = __popc(m);
        __syncthreads();
        if (tid == 0) {
            int acc = 0;
#pragma unroll
            for (int w = 0; w < 8; w++) { wbase[w] = acc; acc += wsum[w]; }
            wbase[8] = acc;
        }
        __syncthreads();
        if (c > 0.f) {
            int pos = base + wbase[wid] + __popc(m & ((1u << lane) - 1u));
            g_idx[e][pos] = n;
            g_wt[e][pos]  = c;
        }
        base += wbase[8];
        __syncthreads();
    }
    if (tid == 0) g_cnt[e] = base;
}

// ---------------- kernel 2b: gather + fp16-round expert inputs into fragment layout ----------------
__global__ __launch_bounds__(256) void permA_kernel(const float* __restrict__ ei)
{
    const int st = blockIdx.x;
    const int e  = blockIdx.y;
    const int me = g_cnt[e];
    if (st * BM >= me) return;
    const int tid = threadIdx.x;
    uint4* dst = (uint4*)g_af;

#pragma unroll 2
    for (int i = 0; i < 64; i++) {
        int idx  = i * 256 + tid;
        int lane = idx & 31;
        int kq   = (idx >> 5) & 63;          // DIM/16 = 64
        int rr   = idx >> 11;                // 0..7
        int g = lane >> 2, t = lane & 3;
        int r = rr * 16 + g;
        int s0 = st * BM + r, s1 = s0 + 8;
        int tok0 = (s0 < me) ? g_idx[e][s0] : 0;
        int tok1 = (s1 < me) ? g_idx[e][s1] : 0;
        const float2* r0 = (const float2*)(ei + ((size_t)e * NTOK + tok0) * DIM);
        const float2* r1 = (const float2*)(ei + ((size_t)e * NTOK + tok1) * DIM);
        float2 a00 = r0[kq * 8 + t];
        float2 a01 = r0[kq * 8 + t + 4];
        float2 a10 = r1[kq * 8 + t];
        float2 a11 = r1[kq * 8 + t + 4];
        uint4 v;
        v.x = pack2(a00.x, a00.y);   // (r,   klo)
        v.y = pack2(a10.x, a10.y);   // (r+8, klo)
        v.z = pack2(a01.x, a01.y);   // (r,   khi)
        v.w = pack2(a11.x, a11.y);   // (r+8, khi)
        dst[(((size_t)(e * 32 + st) * 64 + kq) * 8 + rr) * 32 + lane] = v;
    }
}

// ---------------- kernel 2c: weights -> fp16 B-fragment layout ----------------
// out uint2 (e,kt,G,c8,k2) = { pack2(w[16kt+2k2][8G+c8], w[16kt+2k2+1][8G+c8]),
//                              pack2(w[16kt+2k2+8][8G+c8], w[16kt+2k2+9][8G+c8]) }
__global__ __launch_bounds__(256) void permW_kernel(
    const float* __restrict__ w, uint2* __restrict__ wf, int K, int N)
{
    const int kt = blockIdx.x;
    const int nb = blockIdx.y;
    const int e  = blockIdx.z;
    __shared__ float s[16][132];
    const float* wp = w + (size_t)e * K * N + (size_t)kt * 16 * N + nb * 128;
    const int tid = threadIdx.x;

#pragma unroll
    for (int i = 0; i < 2; i++) {
        int idx = tid + i * 256;            // 0..511 float4 slots (16 rows x 32)
        int row = idx >> 5, c4 = (idx & 31) * 4;
        float4 v = *(const float4*)(wp + (size_t)row * N + c4);
        s[row][c4 + 0] = v.x; s[row][c4 + 1] = v.y;
        s[row][c4 + 2] = v.z; s[row][c4 + 3] = v.w;
    }
    __syncthreads();

    const int NG = N / 8;
    uint2* dst = wf + (((size_t)e * (K / 16) + kt) * NG + nb * 16) * 32;
#pragma unroll
    for (int i = 0; i < 2; i++) {
        int u = tid + i * 256;              // 0..511
        int k2 = u & 3, c8 = (u >> 2) & 7, Gl = u >> 5;
        int n = Gl * 8 + c8;
        uint2 o;
        o.x = pack2(s[2 * k2][n],     s[2 * k2 + 1][n]);
        o.y = pack2(s[2 * k2 + 8][n], s[2 * k2 + 9][n]);
        dst[(size_t)Gl * 32 + c8 * 4 + k2] = o;
    }
}

// =====================================================================================
// FFN GEMMs: 4 warps/CTA (2 wm x 2 wn of 64x64 tiles), CTA 128x128, k-step 16, fp16 MMA.
// NO smem, NO barriers: A and B both direct fragment LDGs from permuted global,
// register double-buffered one kt ahead. Intra-CTA duplicate reads hit L1.
// =====================================================================================

// ---------------- kernel 3: grouped GEMM1: g_hf = frag16(gelu(A @ wf1 + b1)) ----------------
__global__ __launch_bounds__(128, 2) void ffn1_kernel(const float* __restrict__ b1)
{
    const int e  = blockIdx.z;
    const int me = g_cnt[e];
    const int mt = blockIdx.x;
    if (mt * BM >= me) return;
    const int n0 = blockIdx.y * BN;

    const int tid  = threadIdx.x;
    const int lane = tid & 31;
    const int wid  = tid >> 5;
    const int wm   = wid >> 1;
    const int wn   = wid & 1;
    const int g    = lane >> 2;
    const int t    = lane & 3;

    const uint4* aF = (const uint4*)g_af;
    const size_t aB = (size_t)(e * 32 + mt) * 64 * 256 + (wm * 4) * 32 + lane;
    // B fragments: per kt stride = NG*32 = 512*32 = 16384 uint2
    const uint2* bW = g_wf1 + (size_t)e * 64 * 512 * 32
                    + ((size_t)(n0 >> 3) + wn * 8) * 32 + lane;

    float acc[4][8][4];
#pragma unroll
    for (int a = 0; a < 4; a++)
#pragma unroll
        for (int b = 0; b < 8; b++)
#pragma unroll
            for (int q = 0; q < 4; q++) acc[a][b][q] = 0.f;

    uint4 a0[4], a1[4];
    uint2 b0[8], b1r[8];

#pragma unroll
    for (int mi = 0; mi < 4; mi++) a0[mi] = aF[aB + mi * 32];
#pragma unroll
    for (int ni = 0; ni < 8; ni++) b0[ni] = bW[ni * 32];

    const int KT = DIM / 16;   // 64 (even)
    for (int kt = 0; kt < KT; kt += 2) {
#pragma unroll
        for (int mi = 0; mi < 4; mi++)
            a1[mi] = aF[aB + (size_t)(kt + 1) * 256 + mi * 32];
#pragma unroll
        for (int ni = 0; ni < 8; ni++)
            b1r[ni] = bW[(size_t)(kt + 1) * 16384 + ni * 32];
#pragma unroll
        for (int ni = 0; ni < 8; ni++)
#pragma unroll
            for (int mi = 0; mi < 4; mi++)
                mma16(acc[mi][ni], a0[mi], b0[ni]);
        if (kt + 2 < KT) {
#pragma unroll
            for (int mi = 0; mi < 4; mi++)
                a0[mi] = aF[aB + (size_t)(kt + 2) * 256 + mi * 32];
#pragma unroll
            for (int ni = 0; ni < 8; ni++)
                b0[ni] = bW[(size_t)(kt + 2) * 16384 + ni * 32];
        }
#pragma unroll
        for (int ni = 0; ni < 8; ni++)
#pragma unroll
            for (int mi = 0; mi < 4; mi++)
                mma16(acc[mi][ni], a1[mi], b1r[ni]);
    }

    // epilogue: +b1, exact GELU, pack to fp16 fragment layout for GEMM2 (coalesced STG.128)
    float bv[8][2];
#pragma unroll
    for (int ni = 0; ni < 8; ni++) {
        int c = n0 + wn * 64 + ni * 8 + 2 * t;
        bv[ni][0] = b1[e * HID + c];
        bv[ni][1] = b1[e * HID + c + 1];
    }
    uint4* hf = (uint4*)g_hf;
#pragma unroll
    for (int mi = 0; mi < 4; mi++) {
#pragma unroll
        for (int p = 0; p < 4; p++) {
            int n0i = 2 * p, n1i = 2 * p + 1;
            uint4 v;
            v.x = pack2(gelu_exact(acc[mi][n0i][0] + bv[n0i][0]),
                        gelu_exact(acc[mi][n0i][1] + bv[n0i][1]));
            v.y = pack2(gelu_exact(acc[mi][n0i][2] + bv[n0i][0]),
                        gelu_exact(acc[mi][n0i][3] + bv[n0i][1]));
            v.z = pack2(gelu_exact(acc[mi][n1i][0] + bv[n1i][0]),
                        gelu_exact(acc[mi][n1i][1] + bv[n1i][1]));
            v.w = pack2(gelu_exact(acc[mi][n1i][2] + bv[n1i][0]),
                        gelu_exact(acc[mi][n1i][3] + bv[n1i][1]));
            int kq = (n0 >> 4) + wn * 4 + p;
            hf[(((size_t)(e * 32 + mt) * 256 + kq) * 8 + (wm * 4 + mi)) * 32 + lane] = v;
        }
    }
}

// ---------------- kernel 4: grouped GEMM2 (K-split x4): out[tok] += c * (g_hf @ wf2) ----------------
__global__ __launch_bounds__(128, 2) void ffn2_kernel(float* __restrict__ out)
{
    const int e  = blockIdx.z >> 2;
    const int sp = blockIdx.z & 3;
    const int me = g_cnt[e];
    const int mt = blockIdx.x;
    if (mt * BM >= me) return;
    const int n0 = blockIdx.y * BN;

    const int tid  = threadIdx.x;
    const int lane = tid & 31;
    const int wid  = tid >> 5;
    const int wm   = wid >> 1;
    const int wn   = wid & 1;
    const int g    = lane >> 2;
    const int t    = lane & 3;

    const uint4* aF = (const uint4*)g_hf;
    const size_t aB = ((size_t)(e * 32 + mt) * 256 + sp * 64) * 256 + (wm * 4) * 32 + lane;
    // B fragments: NG = DIM/8 = 128 -> per kt stride = 128*32 = 4096 uint2
    const uint2* bW = g_wf2 + (size_t)e * 256 * 128 * 32
                    + ((size_t)(sp * 64) * 128 + (n0 >> 3) + wn * 8) * 32 + lane;

    float acc[4][8][4];
#pragma unroll
    for (int a = 0; a < 4; a++)
#pragma unroll
        for (int b = 0; b < 8; b++)
#pragma unroll
            for (int q = 0; q < 4; q++) acc[a][b][q] = 0.f;

    uint4 a0[4], a1[4];
    uint2 b0[8], b1r[8];

#pragma unroll
    for (int mi = 0; mi < 4; mi++) a0[mi] = aF[aB + mi * 32];
#pragma unroll
    for (int ni = 0; ni < 8; ni++) b0[ni] = bW[ni * 32];

    const int KT = 1024 / 16;   // 64 per split (even)
    for (int kt = 0; kt < KT; kt += 2) {
#pragma unroll
        for (int mi = 0; mi < 4; mi++)
            a1[mi] = aF[aB + (size_t)(kt + 1) * 256 + mi * 32];
#pragma unroll
        for (int ni = 0; ni < 8; ni++)
            b1r[ni] = bW[(size_t)(kt + 1) * 4096 + ni * 32];
#pragma unroll
        for (int ni = 0; ni < 8; ni++)
#pragma unroll
            for (int mi = 0; mi < 4; mi++)
                mma16(acc[mi][ni], a0[mi], b0[ni]);
        if (kt + 2 < KT) {
#pragma unroll
            for (int mi = 0; mi < 4; mi++)
                a0[mi] = aF[aB + (size_t)(kt + 2) * 256 + mi * 32];
#pragma unroll
            for (int ni = 0; ni < 8; ni++)
                b0[ni] = bW[(size_t)(kt + 2) * 4096 + ni * 32];
        }
#pragma unroll
        for (int ni = 0; ni < 8; ni++)
#pragma unroll
            for (int mi = 0; mi < 4; mi++)
                mma16(acc[mi][ni], a1[mi], b1r[ni]);
    }

    // epilogue: scaled scatter-add into fused output (split partials just add)
#pragma unroll
    for (int mi = 0; mi < 4; mi++) {
#pragma unroll
        for (int h2 = 0; h2 < 2; h2++) {
            int row = wm * 64 + mi * 16 + g + 8 * h2;
            int ss = mt * BM + row;
            if (ss < me) {
                int tok  = g_idx[e][ss];
                float wc = g_wt[e][ss];
                float* orow = out + (size_t)tok * DIM;
#pragma unroll
                for (int ni = 0; ni < 8; ni++) {
                    int col = n0 + wn * 64 + ni * 8 + 2 * t;
                    atomicAdd(orow + col,     wc * acc[mi][ni][2 * h2 + 0]);
                    atomicAdd(orow + col + 1, wc * acc[mi][ni][2 * h2 + 1]);
                }
            }
        }
    }
}

// ---------------- launch ----------------
extern "C" void kernel_launch(void* const* d_in, const int* in_sizes, int n_in,
                              void* d_out, int out_size)
{
    (void)in_sizes; (void)n_in; (void)out_size;
    const float* x  = (const float*)d_in[0];
    const float* ei = (const float*)d_in[1];
    const float* wg = (const float*)d_in[2];
    const float* bg = (const float*)d_in[3];
    const float* w1 = (const float*)d_in[4];
    const float* b1 = (const float*)d_in[5];
    const float* w2 = (const float*)d_in[6];
    const float* b2 = (const float*)d_in[7];
    float* out = (float*)d_out;

    uint2* wf1; cudaGetSymbolAddress((void**)&wf1, g_wf1);
    uint2* wf2; cudaGetSymbolAddress((void**)&wf2, g_wf2);

    gate_kernel<<<NTOK / 8, 256>>>(x, wg, bg, b2, out);
    compact_kernel<<<NEXP, 256>>>();
    permA_kernel<<<dim3(NTOK / BM, NEXP), 256>>>(ei);
    permW_kernel<<<dim3(DIM / 16, HID / 128, NEXP), 256>>>(w1, wf1, DIM, HID);
    permW_kernel<<<dim3(HID / 16, DIM / 128, NEXP), 256>>>(w2, wf2, HID, DIM);
    ffn1_kernel<<<dim3(NTOK / BM, HID / BN, NEXP), 128>>>(b1);
    ffn2_kernel<<<dim3(NTOK / BM, DIM / BN, NEXP * 4), 128>>>(out);
}

// round 10
// speedup vs baseline: 1.7544x; 1.0757x over previous
#include <cuda_runtime.h>
#include <cuda_fp16.h>
#include <cstdint>

#define NTOK 4096
#define DIM  1024
#define NEXP 8
#define HID  4096
#define THR  0.3f

#define BM 128
#define BN 128

// ---------------- scratch (static device memory; no allocs anywhere) ----------------
__device__ float g_c[NTOK * NEXP];
__device__ int   g_idx[NEXP][NTOK];
__device__ float g_wt[NEXP][NTOK];
__device__ int   g_cnt[NEXP];
// fp16 A operands in m16n8k16 fragment layout (one uint4 per lane per 16-row x 16-k block)
__device__ __align__(16) uint32_t g_af[(size_t)NEXP * NTOK * DIM / 2];   // half2 units
__device__ __align__(16) uint32_t g_hf[(size_t)NEXP * NTOK * HID / 2];   // half2 units
// fp16 B operands in fragment layout: uint2 per lane per (kt, n-group-of-8)
__device__ __align__(16) uint2 g_wf1[(size_t)NEXP * (DIM / 16) * (HID / 8) * 32];
__device__ __align__(16) uint2 g_wf2[(size_t)NEXP * (HID / 16) * (DIM / 8) * 32];

// ---------------- helpers ----------------
__device__ __forceinline__ uint32_t pack2(float lo, float hi) {
    uint32_t r;
    asm("cvt.rn.f16x2.f32 %0, %1, %2;" : "=r"(r) : "f"(hi), "f"(lo));
    return r;
}

__device__ __forceinline__ void mma16(float* c, const uint4& a, const uint2& b) {
    asm volatile(
        "mma.sync.aligned.m16n8k16.row.col.f32.f16.f16.f32 "
        "{%0,%1,%2,%3}, {%4,%5,%6,%7}, {%8,%9}, {%0,%1,%2,%3};"
        : "+f"(c[0]), "+f"(c[1]), "+f"(c[2]), "+f"(c[3])
        : "r"(a.x), "r"(a.y), "r"(a.z), "r"(a.w), "r"(b.x), "r"(b.y));
}

__device__ __forceinline__ void red_add_v2(float* p, float v0, float v1) {
    asm volatile("red.global.add.v2.f32 [%0], {%1, %2};"
                 :: "l"(p), "f"(v0), "f"(v1) : "memory");
}

__device__ __forceinline__ float gelu_exact(float v) {
    return 0.5f * v * (1.0f + erff(v * 0.70710678118654752f));
}

// ---------------- kernel 1: gate scores, combine weights, out init with sum(c*b2) ----------------
__global__ __launch_bounds__(256) void gate_kernel(
    const float* __restrict__ x, const float* __restrict__ wg,
    const float* __restrict__ bg, const float* __restrict__ b2,
    float* __restrict__ out)
{
    __shared__ float wgs[DIM * 9];
    int tid = threadIdx.x;
    for (int i = tid; i < DIM * NEXP; i += 256)
        wgs[(i >> 3) * 9 + (i & 7)] = wg[i];
    __syncthreads();

    int lane = tid & 31, wid = tid >> 5;
    int n = blockIdx.x * 8 + wid;

    float s[NEXP];
#pragma unroll
    for (int e = 0; e < NEXP; e++) s[e] = 0.f;

    const float* xr = x + (size_t)n * DIM;
    for (int k = lane; k < DIM; k += 32) {
        float xv = xr[k];
#pragma unroll
        for (int e = 0; e < NEXP; e++) s[e] += xv * wgs[k * 9 + e];
    }
#pragma unroll
    for (int e = 0; e < NEXP; e++)
#pragma unroll
        for (int o = 16; o; o >>= 1)
            s[e] += __shfl_xor_sync(0xffffffffu, s[e], o);

    float mx = -1e30f;
#pragma unroll
    for (int e = 0; e < NEXP; e++) { s[e] += bg[e]; mx = fmaxf(mx, s[e]); }
    float sum = 0.f;
#pragma unroll
    for (int e = 0; e < NEXP; e++) { s[e] = expf(s[e] - mx); sum += s[e]; }
    float inv = 1.f / sum;
#pragma unroll
    for (int e = 0; e < NEXP; e++) s[e] *= inv;

    if (lane == 0) {
        float* gs = out + (size_t)NTOK * DIM + (size_t)n * NEXP;
#pragma unroll
        for (int e = 0; e < NEXP; e++) gs[e] = s[e];
    }

    float msum = 0.f; int cnt = 0;
#pragma unroll
    for (int e = 0; e < NEXP; e++) if (s[e] >= THR) { msum += s[e]; cnt++; }
    int top1 = 0; float best = s[0];
#pragma unroll
    for (int e = 1; e < NEXP; e++) if (s[e] > best) { best = s[e]; top1 = e; }
    float dn = 1.f / (msum + 1e-6f);
    float c[NEXP];
#pragma unroll
    for (int e = 0; e < NEXP; e++)
        c[e] = cnt ? ((s[e] >= THR) ? s[e] * dn : 0.f) : ((e == top1) ? 1.f : 0.f);

    if (lane == 0) {
#pragma unroll
        for (int e = 0; e < NEXP; e++) g_c[n * NEXP + e] = c[e];
    }

    for (int d = lane; d < DIM; d += 32) {
        float a = 0.f;
#pragma unroll
        for (int e = 0; e < NEXP; e++) a += c[e] * b2[e * DIM + d];
        out[(size_t)n * DIM + d] = a;
    }
}

// ---------------- kernel 2: per-expert compaction, 1 CTA per expert ----------------
__global__ __launch_bounds__(256) void compact_kernel()
{
    const int e = blockIdx.x;
    __shared__ int wsum[8];
    __shared__ int wbase[9];
    const int tid = threadIdx.x, lane = tid & 31, wid = tid >> 5;

    int base = 0;
#pragma unroll
    for (int c0 = 0; c0 < NTOK; c0 += 256) {
        int n = c0 + tid;
        float c = g_c[n * NEXP + e];
        unsigned m = __ballot_sync(0xffffffffu, c > 0.f);
        if (lane == 0) wsum[wid] = __popc(m);
        __syncthreads();
        if (tid == 0) {
            int acc = 0;
#pragma unroll
            for (int w = 0; w < 8; w++) { wbase[w] = acc; acc += wsum[w]; }
            wbase[8] = acc;
        }
        __syncthreads();
        if (c > 0.f) {
            int pos = base + wbase[wid] + __popc(m & ((1u << lane) - 1u));
            g_idx[e][pos] = n;
            g_wt[e][pos]  = c;
        }
        base += wbase[8];
        __syncthreads();
    }
    if (tid == 0) g_cnt[e] = base;
}

// ---------------- kernel 2b: gather + fp16-round expert inputs into fragment layout ----------------
__global__ __launch_bounds__(256) void permA_kernel(const float* __restrict__ ei)
{
    const int st = blockIdx.x;
    const int e  = blockIdx.y;
    const int me = g_cnt[e];
    if (st * BM >= me) return;
    const int tid = threadIdx.x;
    uint4* dst = (uint4*)g_af;

#pragma unroll 2
    for (int i = 0; i < 64; i++) {
        int idx  = i * 256 + tid;
        int lane = idx & 31;
        int kq   = (idx >> 5) & 63;
        int rr   = idx >> 11;
        int g = lane >> 2, t = lane & 3;
        int r = rr * 16 + g;
        int s0 = st * BM + r, s1 = s0 + 8;
        int tok0 = (s0 < me) ? g_idx[e][s0] : 0;
        int tok1 = (s1 < me) ? g_idx[e][s1] : 0;
        const float2* r0 = (const float2*)(ei + ((size_t)e * NTOK + tok0) * DIM);
        const float2* r1 = (const float2*)(ei + ((size_t)e * NTOK + tok1) * DIM);
        float2 a00 = r0[kq * 8 + t];
        float2 a01 = r0[kq * 8 + t + 4];
        float2 a10 = r1[kq * 8 + t];
        float2 a11 = r1[kq * 8 + t + 4];
        uint4 v;
        v.x = pack2(a00.x, a00.y);
        v.y = pack2(a10.x, a10.y);
        v.z = pack2(a01.x, a01.y);
        v.w = pack2(a11.x, a11.y);
        dst[(((size_t)(e * 32 + st) * 64 + kq) * 8 + rr) * 32 + lane] = v;
    }
}

// ---------------- kernel 2c: weights -> fp16 B-fragment layout ----------------
__global__ __launch_bounds__(256) void permW_kernel(
    const float* __restrict__ w, uint2* __restrict__ wf, int K, int N)
{
    const int kt = blockIdx.x;
    const int nb = blockIdx.y;
    const int e  = blockIdx.z;
    __shared__ float s[16][132];
    const float* wp = w + (size_t)e * K * N + (size_t)kt * 16 * N + nb * 128;
    const int tid = threadIdx.x;

#pragma unroll
    for (int i = 0; i < 2; i++) {
        int idx = tid + i * 256;
        int row = idx >> 5, c4 = (idx & 31) * 4;
        float4 v = *(const float4*)(wp + (size_t)row * N + c4);
        s[row][c4 + 0] = v.x; s[row][c4 + 1] = v.y;
        s[row][c4 + 2] = v.z; s[row][c4 + 3] = v.w;
    }
    __syncthreads();

    const int NG = N / 8;
    uint2* dst = wf + (((size_t)e * (K / 16) + kt) * NG + nb * 16) * 32;
#pragma unroll
    for (int i = 0; i < 2; i++) {
        int u = tid + i * 256;
        int k2 = u & 3, c8 = (u >> 2) & 7, Gl = u >> 5;
        int n = Gl * 8 + c8;
        uint2 o;
        o.x = pack2(s[2 * k2][n],     s[2 * k2 + 1][n]);
        o.y = pack2(s[2 * k2 + 8][n], s[2 * k2 + 9][n]);
        dst[(size_t)Gl * 32 + c8 * 4 + k2] = o;
    }
}

// =====================================================================================
// FFN GEMMs: 4 warps/CTA (2 wm x 2 wn of 64x64 tiles), CTA 128x128, k-step 16, fp16 MMA.
// NO smem, NO barriers: A and B direct fragment LDGs, register double-buffered.
// =====================================================================================

// ---------------- kernel 3: grouped GEMM1: g_hf = frag16(gelu(A @ wf1 + b1)) ----------------
__global__ __launch_bounds__(128, 2) void ffn1_kernel(const float* __restrict__ b1)
{
    const int e  = blockIdx.z;
    const int me = g_cnt[e];
    const int mt = blockIdx.x;
    if (mt * BM >= me) return;
    const int n0 = blockIdx.y * BN;

    const int tid  = threadIdx.x;
    const int lane = tid & 31;
    const int wid  = tid >> 5;
    const int wm   = wid >> 1;
    const int wn   = wid & 1;
    const int g    = lane >> 2;
    const int t    = lane & 3;

    const uint4* aF = (const uint4*)g_af;
    const size_t aB = (size_t)(e * 32 + mt) * 64 * 256 + (wm * 4) * 32 + lane;
    const uint2* bW = g_wf1 + (size_t)e * 64 * 512 * 32
                    + ((size_t)(n0 >> 3) + wn * 8) * 32 + lane;

    float acc[4][8][4];
#pragma unroll
    for (int a = 0; a < 4; a++)
#pragma unroll
        for (int b = 0; b < 8; b++)
#pragma unroll
            for (int q = 0; q < 4; q++) acc[a][b][q] = 0.f;

    uint4 a0[4], a1[4];
    uint2 b0[8], b1r[8];

#pragma unroll
    for (int mi = 0; mi < 4; mi++) a0[mi] = aF[aB + mi * 32];
#pragma unroll
    for (int ni = 0; ni < 8; ni++) b0[ni] = bW[ni * 32];

    const int KT = DIM / 16;   // 64
    for (int kt = 0; kt < KT; kt += 2) {
#pragma unroll
        for (int mi = 0; mi < 4; mi++)
            a1[mi] = aF[aB + (size_t)(kt + 1) * 256 + mi * 32];
#pragma unroll
        for (int ni = 0; ni < 8; ni++)
            b1r[ni] = bW[(size_t)(kt + 1) * 16384 + ni * 32];
#pragma unroll
        for (int ni = 0; ni < 8; ni++)
#pragma unroll
            for (int mi = 0; mi < 4; mi++)
                mma16(acc[mi][ni], a0[mi], b0[ni]);
        if (kt + 2 < KT) {
#pragma unroll
            for (int mi = 0; mi < 4; mi++)
                a0[mi] = aF[aB + (size_t)(kt + 2) * 256 + mi * 32];
#pragma unroll
            for (int ni = 0; ni < 8; ni++)
                b0[ni] = bW[(size_t)(kt + 2) * 16384 + ni * 32];
        }
#pragma unroll
        for (int ni = 0; ni < 8; ni++)
#pragma unroll
            for (int mi = 0; mi < 4; mi++)
                mma16(acc[mi][ni], a1[mi], b1r[ni]);
    }

    // epilogue: +b1, exact GELU, pack to fp16 fragment layout for GEMM2
    float bv[8][2];
#pragma unroll
    for (int ni = 0; ni < 8; ni++) {
        int c = n0 + wn * 64 + ni * 8 + 2 * t;
        bv[ni][0] = b1[e * HID + c];
        bv[ni][1] = b1[e * HID + c + 1];
    }
    uint4* hf = (uint4*)g_hf;
#pragma unroll
    for (int mi = 0; mi < 4; mi++) {
#pragma unroll
        for (int p = 0; p < 4; p++) {
            int n0i = 2 * p, n1i = 2 * p + 1;
            uint4 v;
            v.x = pack2(gelu_exact(acc[mi][n0i][0] + bv[n0i][0]),
                        gelu_exact(acc[mi][n0i][1] + bv[n0i][1]));
            v.y = pack2(gelu_exact(acc[mi][n0i][2] + bv[n0i][0]),
                        gelu_exact(acc[mi][n0i][3] + bv[n0i][1]));
            v.z = pack2(gelu_exact(acc[mi][n1i][0] + bv[n1i][0]),
                        gelu_exact(acc[mi][n1i][1] + bv[n1i][1]));
            v.w = pack2(gelu_exact(acc[mi][n1i][2] + bv[n1i][0]),
                        gelu_exact(acc[mi][n1i][3] + bv[n1i][1]));
            int kq = (n0 >> 4) + wn * 4 + p;
            hf[(((size_t)(e * 32 + mt) * 256 + kq) * 8 + (wm * 4 + mi)) * 32 + lane] = v;
        }
    }
}

// ---------------- kernel 4: grouped GEMM2 (full K): out[tok] += c * (g_hf @ wf2) ----------------
__global__ __launch_bounds__(128, 2) void ffn2_kernel(float* __restrict__ out)
{
    const int e  = blockIdx.z;
    const int me = g_cnt[e];
    const int mt = blockIdx.x;
    if (mt * BM >= me) return;
    const int n0 = blockIdx.y * BN;

    const int tid  = threadIdx.x;
    const int lane = tid & 31;
    const int wid  = tid >> 5;
    const int wm   = wid >> 1;
    const int wn   = wid & 1;
    const int g    = lane >> 2;
    const int t    = lane & 3;

    const uint4* aF = (const uint4*)g_hf;
    const size_t aB = (size_t)(e * 32 + mt) * 256 * 256 + (wm * 4) * 32 + lane;
    // B fragments: NG = DIM/8 = 128 -> per kt stride = 128*32 = 4096 uint2
    const uint2* bW = g_wf2 + (size_t)e * 256 * 128 * 32
                    + ((size_t)(n0 >> 3) + wn * 8) * 32 + lane;

    float acc[4][8][4];
#pragma unroll
    for (int a = 0; a < 4; a++)
#pragma unroll
        for (int b = 0; b < 8; b++)
#pragma unroll
            for (int q = 0; q < 4; q++) acc[a][b][q] = 0.f;

    uint4 a0[4], a1[4];
    uint2 b0[8], b1r[8];

#pragma unroll
    for (int mi = 0; mi < 4; mi++) a0[mi] = aF[aB + mi * 32];
#pragma unroll
    for (int ni = 0; ni < 8; ni++) b0[ni] = bW[ni * 32];

    const int KT = HID / 16;   // 256
    for (int kt = 0; kt < KT; kt += 2) {
#pragma unroll
        for (int mi = 0; mi < 4; mi++)
            a1[mi] = aF[aB + (size_t)(kt + 1) * 256 + mi * 32];
#pragma unroll
        for (int ni = 0; ni < 8; ni++)
            b1r[ni] = bW[(size_t)(kt + 1) * 4096 + ni * 32];
#pragma unroll
        for (int ni = 0; ni < 8; ni++)
#pragma unroll
            for (int mi = 0; mi < 4; mi++)
                mma16(acc[mi][ni], a0[mi], b0[ni]);
        if (kt + 2 < KT) {
#pragma unroll
            for (int mi = 0; mi < 4; mi++)
                a0[mi] = aF[aB + (size_t)(kt + 2) * 256 + mi * 32];
#pragma unroll
            for (int ni = 0; ni < 8; ni++)
                b0[ni] = bW[(size_t)(kt + 2) * 4096 + ni * 32];
        }
#pragma unroll
        for (int ni = 0; ni < 8; ni++)
#pragma unroll
            for (int mi = 0; mi < 4; mi++)
                mma16(acc[mi][ni], a1[mi], b1r[ni]);
    }

    // epilogue: scaled vector scatter-add (red.global.add.v2.f32)
#pragma unroll
    for (int mi = 0; mi < 4; mi++) {
#pragma unroll
        for (int h2 = 0; h2 < 2; h2++) {
            int row = wm * 64 + mi * 16 + g + 8 * h2;
            int ss = mt * BM + row;
            if (ss < me) {
                int tok  = g_idx[e][ss];
                float wc = g_wt[e][ss];
                float* orow = out + (size_t)tok * DIM;
#pragma unroll
                for (int ni = 0; ni < 8; ni++) {
                    int col = n0 + wn * 64 + ni * 8 + 2 * t;
                    red_add_v2(orow + col,
                               wc * acc[mi][ni][2 * h2 + 0],
                               wc * acc[mi][ni][2 * h2 + 1]);
                }
            }
        }
    }
}

// ---------------- launch ----------------
extern "C" void kernel_launch(void* const* d_in, const int* in_sizes, int n_in,
                              void* d_out, int out_size)
{
    (void)in_sizes; (void)n_in; (void)out_size;
    const float* x  = (const float*)d_in[0];
    const float* ei = (const float*)d_in[1];
    const float* wg = (const float*)d_in[2];
    const float* bg = (const float*)d_in[3];
    const float* w1 = (const float*)d_in[4];
    const float* b1 = (const float*)d_in[5];
    const float* w2 = (const float*)d_in[6];
    const float* b2 = (const float*)d_in[7];
    float* out = (float*)d_out;

    uint2* wf1; cudaGetSymbolAddress((void**)&wf1, g_wf1);
    uint2* wf2; cudaGetSymbolAddress((void**)&wf2, g_wf2);

    // lazily-created side stream + events (resource setup only; captured work is
    // identical on every call -> deterministic graph)
    static cudaStream_t s_aux = nullptr;
    static cudaEvent_t ev_fork = nullptr, ev_join = nullptr;
    if (!s_aux) {
        cudaStreamCreateWithFlags(&s_aux, cudaStreamNonBlocking);
        cudaEventCreateWithFlags(&ev_fork, cudaEventDisableTiming);
        cudaEventCreateWithFlags(&ev_join, cudaEventDisableTiming);
    }

    // fork: weight permutation runs on side stream, overlapping the gate chain
    cudaEventRecord(ev_fork, 0);
    cudaStreamWaitEvent(s_aux, ev_fork, 0);
    permW_kernel<<<dim3(DIM / 16, HID / 128, NEXP), 256, 0, s_aux>>>(w1, wf1, DIM, HID);
    permW_kernel<<<dim3(HID / 16, DIM / 128, NEXP), 256, 0, s_aux>>>(w2, wf2, HID, DIM);
    cudaEventRecord(ev_join, s_aux);

    gate_kernel<<<NTOK / 8, 256>>>(x, wg, bg, b2, out);
    compact_kernel<<<NEXP, 256>>>();
    permA_kernel<<<dim3(NTOK / BM, NEXP), 256>>>(ei);

    // join before GEMMs consume permuted weights
    cudaStreamWaitEvent(0, ev_join, 0);
    ffn1_kernel<<<dim3(NTOK / BM, HID / BN, NEXP), 128>>>(b1);
    ffn2_kernel<<<dim3(NTOK / BM, DIM / BN, NEXP), 128>>>(out);
}

// round 11
// speedup vs baseline: 1.7676x; 1.0075x over previous
#include <cuda_runtime.h>
#include <cuda_fp16.h>
#include <cstdint>

#define NTOK 4096
#define DIM  1024
#define NEXP 8
#define HID  4096
#define THR  0.3f

#define BM 128
#define BN 128

// ---------------- scratch (static device memory; no allocs anywhere) ----------------
__device__ float g_c[NTOK * NEXP];
__device__ int   g_idx[NEXP][NTOK];
__device__ float g_wt[NEXP][NTOK];
__device__ int   g_cnt[NEXP];
// fp16 A operands in m16n8k16 fragment layout (one uint4 per lane per 16-row x 16-k block)
__device__ __align__(16) uint32_t g_af[(size_t)NEXP * NTOK * DIM / 2];   // half2 units
__device__ __align__(16) uint32_t g_hf[(size_t)NEXP * NTOK * HID / 2];   // half2 units
// fp16 B operands in fragment layout: uint2 per lane per (kt, n-group-of-8)
__device__ __align__(16) uint2 g_wf1[(size_t)NEXP * (DIM / 16) * (HID / 8) * 32];
__device__ __align__(16) uint2 g_wf2[(size_t)NEXP * (HID / 16) * (DIM / 8) * 32];

// ---------------- helpers ----------------
__device__ __forceinline__ uint32_t pack2(float lo, float hi) {
    uint32_t r;
    asm("cvt.rn.f16x2.f32 %0, %1, %2;" : "=r"(r) : "f"(hi), "f"(lo));
    return r;
}

__device__ __forceinline__ void mma16(float* c, const uint4& a, const uint2& b) {
    asm volatile(
        "mma.sync.aligned.m16n8k16.row.col.f32.f16.f16.f32 "
        "{%0,%1,%2,%3}, {%4,%5,%6,%7}, {%8,%9}, {%0,%1,%2,%3};"
        : "+f"(c[0]), "+f"(c[1]), "+f"(c[2]), "+f"(c[3])
        : "r"(a.x), "r"(a.y), "r"(a.z), "r"(a.w), "r"(b.x), "r"(b.y));
}

__device__ __forceinline__ void red_add_v2(float* p, float v0, float v1) {
    asm volatile("red.global.add.v2.f32 [%0], {%1, %2};"
                 :: "l"(p), "f"(v0), "f"(v1) : "memory");
}

__device__ __forceinline__ float gelu_exact(float v) {
    return 0.5f * v * (1.0f + erff(v * 0.70710678118654752f));
}

// ---------------- kernel 1: gate scores, combine weights, out init with sum(c*b2) ----------------
__global__ __launch_bounds__(256) void gate_kernel(
    const float* __restrict__ x, const float* __restrict__ wg,
    const float* __restrict__ bg, const float* __restrict__ b2,
    float* __restrict__ out)
{
    __shared__ float wgs[DIM * 9];
    int tid = threadIdx.x;
    for (int i = tid; i < DIM * NEXP; i += 256)
        wgs[(i >> 3) * 9 + (i & 7)] = wg[i];
    __syncthreads();

    int lane = tid & 31, wid = tid >> 5;
    int n = blockIdx.x * 8 + wid;

    float s[NEXP];
#pragma unroll
    for (int e = 0; e < NEXP; e++) s[e] = 0.f;

    const float* xr = x + (size_t)n * DIM;
    for (int k = lane; k < DIM; k += 32) {
        float xv = xr[k];
#pragma unroll
        for (int e = 0; e < NEXP; e++) s[e] += xv * wgs[k * 9 + e];
    }
#pragma unroll
    for (int e = 0; e < NEXP; e++)
#pragma unroll
        for (int o = 16; o; o >>= 1)
            s[e] += __shfl_xor_sync(0xffffffffu, s[e], o);

    float mx = -1e30f;
#pragma unroll
    for (int e = 0; e < NEXP; e++) { s[e] += bg[e]; mx = fmaxf(mx, s[e]); }
    float sum = 0.f;
#pragma unroll
    for (int e = 0; e < NEXP; e++) { s[e] = expf(s[e] - mx); sum += s[e]; }
    float inv = 1.f / sum;
#pragma unroll
    for (int e = 0; e < NEXP; e++) s[e] *= inv;

    if (lane == 0) {
        float* gs = out + (size_t)NTOK * DIM + (size_t)n * NEXP;
#pragma unroll
        for (int e = 0; e < NEXP; e++) gs[e] = s[e];
    }

    float msum = 0.f; int cnt = 0;
#pragma unroll
    for (int e = 0; e < NEXP; e++) if (s[e] >= THR) { msum += s[e]; cnt++; }
    int top1 = 0; float best = s[0];
#pragma unroll
    for (int e = 1; e < NEXP; e++) if (s[e] > best) { best = s[e]; top1 = e; }
    float dn = 1.f / (msum + 1e-6f);
    float c[NEXP];
#pragma unroll
    for (int e = 0; e < NEXP; e++)
        c[e] = cnt ? ((s[e] >= THR) ? s[e] * dn : 0.f) : ((e == top1) ? 1.f : 0.f);

    if (lane == 0) {
#pragma unroll
        for (int e = 0; e < NEXP; e++) g_c[n * NEXP + e] = c[e];
    }

    for (int d = lane; d < DIM; d += 32) {
        float a = 0.f;
#pragma unroll
        for (int e = 0; e < NEXP; e++) a += c[e] * b2[e * DIM + d];
        out[(size_t)n * DIM + d] = a;
    }
}

// ---------------- kernel 2: per-expert compaction, 1 CTA per expert, 2 barriers ----------------
__global__ __launch_bounds__(256) void compact_kernel()
{
    const int e = blockIdx.x;
    const int tid = threadIdx.x, lane = tid & 31, wid = tid >> 5;
    __shared__ unsigned masks[8][16];
    __shared__ int wbase[8];

    const int base0 = wid * 512;
    int cnt = 0;
#pragma unroll
    for (int i = 0; i < 16; i++) {
        int n = base0 + i * 32 + lane;
        float c = g_c[n * NEXP + e];
        unsigned m = __ballot_sync(0xffffffffu, c > 0.f);
        if (lane == 0) masks[wid][i] = m;
        cnt += __popc(m);
    }
    __shared__ int wcnt[8];
    if (lane == 0) wcnt[wid] = cnt;
    __syncthreads();
    if (tid == 0) {
        int acc = 0;
#pragma unroll
        for (int w = 0; w < 8; w++) { wbase[w] = acc; acc += wcnt[w]; }
        g_cnt[e] = acc;
    }
    __syncthreads();

    int pos = wbase[wid];
#pragma unroll
    for (int i = 0; i < 16; i++) {
        unsigned m = masks[wid][i];
        if ((m >> lane) & 1u) {
            int n = base0 + i * 32 + lane;
            int p = pos + __popc(m & ((1u << lane) - 1u));
            g_idx[e][p] = n;
            g_wt[e][p]  = g_c[n * NEXP + e];
        }
        pos += __popc(m);
    }
}

// ---------------- kernel 2b: gather + fp16-round expert inputs into fragment layout ----------------
__global__ __launch_bounds__(256) void permA_kernel(const float* __restrict__ ei)
{
    const int st = blockIdx.x;
    const int e  = blockIdx.y;
    const int me = g_cnt[e];
    if (st * BM >= me) return;
    const int tid = threadIdx.x;
    uint4* dst = (uint4*)g_af;

#pragma unroll 2
    for (int i = 0; i < 64; i++) {
        int idx  = i * 256 + tid;
        int lane = idx & 31;
        int kq   = (idx >> 5) & 63;
        int rr   = idx >> 11;
        int g = lane >> 2, t = lane & 3;
        int r = rr * 16 + g;
        int s0 = st * BM + r, s1 = s0 + 8;
        int tok0 = (s0 < me) ? g_idx[e][s0] : 0;
        int tok1 = (s1 < me) ? g_idx[e][s1] : 0;
        const float2* r0 = (const float2*)(ei + ((size_t)e * NTOK + tok0) * DIM);
        const float2* r1 = (const float2*)(ei + ((size_t)e * NTOK + tok1) * DIM);
        float2 a00 = r0[kq * 8 + t];
        float2 a01 = r0[kq * 8 + t + 4];
        float2 a10 = r1[kq * 8 + t];
        float2 a11 = r1[kq * 8 + t + 4];
        uint4 v;
        v.x = pack2(a00.x, a00.y);
        v.y = pack2(a10.x, a10.y);
        v.z = pack2(a01.x, a01.y);
        v.w = pack2(a11.x, a11.y);
        dst[(((size_t)(e * 32 + st) * 64 + kq) * 8 + rr) * 32 + lane] = v;
    }
}

// ---------------- kernel 2c: weights -> fp16 B-fragment layout ----------------
__global__ __launch_bounds__(256) void permW_kernel(
    const float* __restrict__ w, uint2* __restrict__ wf, int K, int N)
{
    const int kt = blockIdx.x;
    const int nb = blockIdx.y;
    const int e  = blockIdx.z;
    __shared__ float s[16][132];
    const float* wp = w + (size_t)e * K * N + (size_t)kt * 16 * N + nb * 128;
    const int tid = threadIdx.x;

#pragma unroll
    for (int i = 0; i < 2; i++) {
        int idx = tid + i * 256;
        int row = idx >> 5, c4 = (idx & 31) * 4;
        float4 v = *(const float4*)(wp + (size_t)row * N + c4);
        s[row][c4 + 0] = v.x; s[row][c4 + 1] = v.y;
        s[row][c4 + 2] = v.z; s[row][c4 + 3] = v.w;
    }
    __syncthreads();

    const int NG = N / 8;
    uint2* dst = wf + (((size_t)e * (K / 16) + kt) * NG + nb * 16) * 32;
#pragma unroll
    for (int i = 0; i < 2; i++) {
        int u = tid + i * 256;
        int k2 = u & 3, c8 = (u >> 2) & 7, Gl = u >> 5;
        int n = Gl * 8 + c8;
        uint2 o;
        o.x = pack2(s[2 * k2][n],     s[2 * k2 + 1][n]);
        o.y = pack2(s[2 * k2 + 8][n], s[2 * k2 + 9][n]);
        dst[(size_t)Gl * 32 + c8 * 4 + k2] = o;
    }
}

// =====================================================================================
// FFN GEMMs: 4 warps/CTA (2 wm x 2 wn of 64x64 tiles), CTA 128x128, k-step 16, fp16 MMA.
// NO smem, NO barriers: A and B direct fragment LDGs, register double-buffered.
// =====================================================================================

// ---------------- kernel 3: grouped GEMM1: g_hf = frag16(gelu(A @ wf1 + b1)) ----------------
__global__ __launch_bounds__(128, 2) void ffn1_kernel(const float* __restrict__ b1)
{
    const int e  = blockIdx.z;
    const int me = g_cnt[e];
    const int mt = blockIdx.x;
    if (mt * BM >= me) return;
    const int n0 = blockIdx.y * BN;

    const int tid  = threadIdx.x;
    const int lane = tid & 31;
    const int wid  = tid >> 5;
    const int wm   = wid >> 1;
    const int wn   = wid & 1;
    const int g    = lane >> 2;
    const int t    = lane & 3;

    const uint4* aF = (const uint4*)g_af;
    const size_t aB = (size_t)(e * 32 + mt) * 64 * 256 + (wm * 4) * 32 + lane;
    const uint2* bW = g_wf1 + (size_t)e * 64 * 512 * 32
                    + ((size_t)(n0 >> 3) + wn * 8) * 32 + lane;

    float acc[4][8][4];
#pragma unroll
    for (int a = 0; a < 4; a++)
#pragma unroll
        for (int b = 0; b < 8; b++)
#pragma unroll
            for (int q = 0; q < 4; q++) acc[a][b][q] = 0.f;

    uint4 a0[4], a1[4];
    uint2 b0[8], b1r[8];

#pragma unroll
    for (int mi = 0; mi < 4; mi++) a0[mi] = aF[aB + mi * 32];
#pragma unroll
    for (int ni = 0; ni < 8; ni++) b0[ni] = bW[ni * 32];

    const int KT = DIM / 16;   // 64
    for (int kt = 0; kt < KT; kt += 2) {
#pragma unroll
        for (int mi = 0; mi < 4; mi++)
            a1[mi] = aF[aB + (size_t)(kt + 1) * 256 + mi * 32];
#pragma unroll
        for (int ni = 0; ni < 8; ni++)
            b1r[ni] = bW[(size_t)(kt + 1) * 16384 + ni * 32];
#pragma unroll
        for (int ni = 0; ni < 8; ni++)
#pragma unroll
            for (int mi = 0; mi < 4; mi++)
                mma16(acc[mi][ni], a0[mi], b0[ni]);
        if (kt + 2 < KT) {
#pragma unroll
            for (int mi = 0; mi < 4; mi++)
                a0[mi] = aF[aB + (size_t)(kt + 2) * 256 + mi * 32];
#pragma unroll
            for (int ni = 0; ni < 8; ni++)
                b0[ni] = bW[(size_t)(kt + 2) * 16384 + ni * 32];
        }
#pragma unroll
        for (int ni = 0; ni < 8; ni++)
#pragma unroll
            for (int mi = 0; mi < 4; mi++)
                mma16(acc[mi][ni], a1[mi], b1r[ni]);
    }

    // epilogue: +b1, exact GELU, pack to fp16 fragment layout for GEMM2
    float bv[8][2];
#pragma unroll
    for (int ni = 0; ni < 8; ni++) {
        int c = n0 + wn * 64 + ni * 8 + 2 * t;
        bv[ni][0] = b1[e * HID + c];
        bv[ni][1] = b1[e * HID + c + 1];
    }
    uint4* hf = (uint4*)g_hf;
#pragma unroll
    for (int mi = 0; mi < 4; mi++) {
#pragma unroll
        for (int p = 0; p < 4; p++) {
            int n0i = 2 * p, n1i = 2 * p + 1;
            uint4 v;
            v.x = pack2(gelu_exact(acc[mi][n0i][0] + bv[n0i][0]),
                        gelu_exact(acc[mi][n0i][1] + bv[n0i][1]));
            v.y = pack2(gelu_exact(acc[mi][n0i][2] + bv[n0i][0]),
                        gelu_exact(acc[mi][n0i][3] + bv[n0i][1]));
            v.z = pack2(gelu_exact(acc[mi][n1i][0] + bv[n1i][0]),
                        gelu_exact(acc[mi][n1i][1] + bv[n1i][1]));
            v.w = pack2(gelu_exact(acc[mi][n1i][2] + bv[n1i][0]),
                        gelu_exact(acc[mi][n1i][3] + bv[n1i][1]));
            int kq = (n0 >> 4) + wn * 4 + p;
            hf[(((size_t)(e * 32 + mt) * 256 + kq) * 8 + (wm * 4 + mi)) * 32 + lane] = v;
        }
    }
}

// ---------------- kernel 4: grouped GEMM2 (K-split x2): out[tok] += c * (g_hf @ wf2) ----------------
__global__ __launch_bounds__(128, 2) void ffn2_kernel(float* __restrict__ out)
{
    const int e  = blockIdx.z >> 1;
    const int sp = blockIdx.z & 1;
    const int me = g_cnt[e];
    const int mt = blockIdx.x;
    if (mt * BM >= me) return;
    const int n0 = blockIdx.y * BN;

    const int tid  = threadIdx.x;
    const int lane = tid & 31;
    const int wid  = tid >> 5;
    const int wm   = wid >> 1;
    const int wn   = wid & 1;
    const int g    = lane >> 2;
    const int t    = lane & 3;

    const uint4* aF = (const uint4*)g_hf;
    const size_t aB = (size_t)(e * 32 + mt) * 256 * 256 + (size_t)(sp * 128) * 256
                    + (wm * 4) * 32 + lane;
    // B fragments: NG = DIM/8 = 128 -> per kt stride = 128*32 = 4096 uint2
    const uint2* bW = g_wf2 + (size_t)e * 256 * 128 * 32 + (size_t)(sp * 128) * 4096
                    + ((size_t)(n0 >> 3) + wn * 8) * 32 + lane;

    float acc[4][8][4];
#pragma unroll
    for (int a = 0; a < 4; a++)
#pragma unroll
        for (int b = 0; b < 8; b++)
#pragma unroll
            for (int q = 0; q < 4; q++) acc[a][b][q] = 0.f;

    uint4 a0[4], a1[4];
    uint2 b0[8], b1r[8];

#pragma unroll
    for (int mi = 0; mi < 4; mi++) a0[mi] = aF[aB + mi * 32];
#pragma unroll
    for (int ni = 0; ni < 8; ni++) b0[ni] = bW[ni * 32];

    const int KT = (HID / 2) / 16;   // 128 per split
    for (int kt = 0; kt < KT; kt += 2) {
#pragma unroll
        for (int mi = 0; mi < 4; mi++)
            a1[mi] = aF[aB + (size_t)(kt + 1) * 256 + mi * 32];
#pragma unroll
        for (int ni = 0; ni < 8; ni++)
            b1r[ni] = bW[(size_t)(kt + 1) * 4096 + ni * 32];
#pragma unroll
        for (int ni = 0; ni < 8; ni++)
#pragma unroll
            for (int mi = 0; mi < 4; mi++)
                mma16(acc[mi][ni], a0[mi], b0[ni]);
        if (kt + 2 < KT) {
#pragma unroll
            for (int mi = 0; mi < 4; mi++)
                a0[mi] = aF[aB + (size_t)(kt + 2) * 256 + mi * 32];
#pragma unroll
            for (int ni = 0; ni < 8; ni++)
                b0[ni] = bW[(size_t)(kt + 2) * 4096 + ni * 32];
        }
#pragma unroll
        for (int ni = 0; ni < 8; ni++)
#pragma unroll
            for (int mi = 0; mi < 4; mi++)
                mma16(acc[mi][ni], a1[mi], b1r[ni]);
    }

    // epilogue: scaled vector scatter-add (red.global.add.v2.f32); split partials add
#pragma unroll
    for (int mi = 0; mi < 4; mi++) {
#pragma unroll
        for (int h2 = 0; h2 < 2; h2++) {
            int row = wm * 64 + mi * 16 + g + 8 * h2;
            int ss = mt * BM + row;
            if (ss < me) {
                int tok  = g_idx[e][ss];
                float wc = g_wt[e][ss];
                float* orow = out + (size_t)tok * DIM;
#pragma unroll
                for (int ni = 0; ni < 8; ni++) {
                    int col = n0 + wn * 64 + ni * 8 + 2 * t;
                    red_add_v2(orow + col,
                               wc * acc[mi][ni][2 * h2 + 0],
                               wc * acc[mi][ni][2 * h2 + 1]);
                }
            }
        }
    }
}

// ---------------- launch ----------------
extern "C" void kernel_launch(void* const* d_in, const int* in_sizes, int n_in,
                              void* d_out, int out_size)
{
    (void)in_sizes; (void)n_in; (void)out_size;
    const float* x  = (const float*)d_in[0];
    const float* ei = (const float*)d_in[1];
    const float* wg = (const float*)d_in[2];
    const float* bg = (const float*)d_in[3];
    const float* w1 = (const float*)d_in[4];
    const float* b1 = (const float*)d_in[5];
    const float* w2 = (const float*)d_in[6];
    const float* b2 = (const float*)d_in[7];
    float* out = (float*)d_out;

    uint2* wf1; cudaGetSymbolAddress((void**)&wf1, g_wf1);
    uint2* wf2; cudaGetSymbolAddress((void**)&wf2, g_wf2);

    // lazily-created side stream + events (resource setup only; captured work is
    // identical on every call -> deterministic graph)
    static cudaStream_t s_aux = nullptr;
    static cudaEvent_t ev_fork = nullptr, ev_join = nullptr;
    if (!s_aux) {
        cudaStreamCreateWithFlags(&s_aux, cudaStreamNonBlocking);
        cudaEventCreateWithFlags(&ev_fork, cudaEventDisableTiming);
        cudaEventCreateWithFlags(&ev_join, cudaEventDisableTiming);
    }

    // fork: weight permutation runs on side stream, overlapping the gate chain
    cudaEventRecord(ev_fork, 0);
    cudaStreamWaitEvent(s_aux, ev_fork, 0);
    permW_kernel<<<dim3(DIM / 16, HID / 128, NEXP), 256, 0, s_aux>>>(w1, wf1, DIM, HID);
    permW_kernel<<<dim3(HID / 16, DIM / 128, NEXP), 256, 0, s_aux>>>(w2, wf2, HID, DIM);
    cudaEventRecord(ev_join, s_aux);

    gate_kernel<<<NTOK / 8, 256>>>(x, wg, bg, b2, out);
    compact_kernel<<<NEXP, 256>>>();
    permA_kernel<<<dim3(NTOK / BM, NEXP), 256>>>(ei);

    // join before GEMMs consume permuted weights
    cudaStreamWaitEvent(0, ev_join, 0);
    ffn1_kernel<<<dim3(NTOK / BM, HID / BN, NEXP), 128>>>(b1);
    ffn2_kernel<<<dim3(NTOK / BM, DIM / BN, NEXP * 2), 128>>>(out);
}